// round 14
// baseline (speedup 1.0000x reference)
#include <cuda_runtime.h>
#include <cuda_bf16.h>
#include <cstdint>

#define N_NODES 100000
#define N_EDGES 1600000
#define HID 128
#define GG 512
#define XSD 384
#define NB64 1563                       // ceil(100000/64)
#define GRID_MMA 296                    // persistent: 2 CTAs/SM x 148 SMs
#define KP 136                          // smem pitch in bf16 elems
#define A64 (64 * KP)                   // elems per 64-row A image
#define B128 (128 * KP)                 // elems per 128-row B image
#define SMEM_BYTES ((2 * A64 + 2 * B128) * 2 + 1024)   // 105472
#define NBLK1 98                        // ceil(100000/1024)
#define HIST_BLKS 6250

// ---------------- scratch (static device globals; no allocation) ----------------
__device__ float g_y[N_NODES * HID];      // pre-aggregation features (gather source)
__device__ float g_agg[N_NODES * HID];    // self + edge aggregation
__device__ float g_xs[N_NODES * XSD];     // per-layer raw (pre-BN-affine) outputs
__device__ uint4 g_wimg[6 * 4352];        // 6 weights x (hi+lo) bf16 images [n][k] pitch KP
__device__ float g_pooled[GG * XSD];
__device__ float g_sum[3 * HID];
__device__ float g_sumsq[3 * HID];
__device__ int   g_counts[GG];
// CSR scratch
__device__ int g_deg[NBLK1 * 1024];
__device__ int g_incl[NBLK1 * 1024];
__device__ int g_start[N_NODES];
__device__ int g_cur[N_NODES];
__device__ int g_ssrc[N_EDGES];
__device__ int g_bsum[128];

// ---------------- helpers ----------------
__device__ __forceinline__ void red_add_v4(float* p, float4 v) {
    asm volatile("red.global.add.v4.f32 [%0], {%1, %2, %3, %4};"
                 :: "l"(p), "f"(v.x), "f"(v.y), "f"(v.z), "f"(v.w) : "memory");
}
__device__ __forceinline__ void mma_bf16(float* c, uint32_t a0, uint32_t a1, uint32_t a2,
                                         uint32_t a3, uint32_t b0, uint32_t b1) {
    asm volatile(
        "mma.sync.aligned.m16n8k16.row.col.f32.bf16.bf16.f32 "
        "{%0,%1,%2,%3}, {%4,%5,%6,%7}, {%8,%9}, {%0,%1,%2,%3};"
        : "+f"(c[0]), "+f"(c[1]), "+f"(c[2]), "+f"(c[3])
        : "r"(a0), "r"(a1), "r"(a2), "r"(a3), "r"(b0), "r"(b1));
}
__device__ __forceinline__ void ldsm_x4(uint32_t* r, uint32_t addr) {
    asm volatile("ldmatrix.sync.aligned.m8n8.x4.shared.b16 {%0,%1,%2,%3}, [%4];"
                 : "=r"(r[0]), "=r"(r[1]), "=r"(r[2]), "=r"(r[3]) : "r"(addr));
}
__device__ __forceinline__ uint32_t pack_bf2(__nv_bfloat16 lo, __nv_bfloat16 hi) {
    return (uint32_t)__bfloat16_as_ushort(lo) | ((uint32_t)__bfloat16_as_ushort(hi) << 16);
}

// ---------------- weight prep + stat/pool/deg zero ----------------
__global__ void k_prep(const float* __restrict__ w0, const float* __restrict__ w1,
                       const float* __restrict__ w2, const float* __restrict__ w3,
                       const float* __restrict__ w4, const float* __restrict__ w5) {
    int bb = blockIdx.x;
    if (bb < 6) {
        const float* W = bb == 0 ? w0 : bb == 1 ? w1 : bb == 2 ? w2 : bb == 3 ? w3 : bb == 4 ? w4 : w5;
        __nv_bfloat16* img = ((__nv_bfloat16*)g_wimg) + (size_t)bb * 2 * B128;
        for (int idx = threadIdx.x; idx < 16384; idx += 256) {
            int k = idx >> 7, n = idx & 127;
            float w = W[idx];
            __nv_bfloat16 h = __float2bfloat16(w);
            __nv_bfloat16 l = __float2bfloat16(w - __bfloat162float(h));
            img[n * KP + k] = h;
            img[B128 + n * KP + k] = l;
        }
    } else if (bb == 6) {
        for (int i = threadIdx.x; i < 3 * HID; i += 256) { g_sum[i] = 0.f; g_sumsq[i] = 0.f; }
    } else if (bb < 199) {
        int idx = (bb - 7) * 256 + threadIdx.x;
        if (idx < GG * XSD / 4) ((float4*)g_pooled)[idx] = make_float4(0.f, 0.f, 0.f, 0.f);
    } else {
        int base = (bb - 199) * 1024 + threadIdx.x * 4;
        *(int4*)&g_deg[base] = make_int4(0, 0, 0, 0);
    }
}

// ---------------- CSR hist + graph counts (merged) ----------------
__global__ void k_hist(const int* __restrict__ dst, const int* __restrict__ batch) {
    if (blockIdx.x < HIST_BLKS) {
        int e = blockIdx.x * 256 + threadIdx.x;
        if (e < N_EDGES) atomicAdd(&g_deg[dst[e]], 1);
    } else {
        __shared__ int h[GG];
        int t = threadIdx.x;
        for (int i = t; i < GG; i += 256) h[i] = 0;
        __syncthreads();
        for (int i = t; i < N_NODES; i += 256) atomicAdd(&h[batch[i]], 1);
        __syncthreads();
        for (int i = t; i < GG; i += 256) g_counts[i] = h[i];
    }
}

__global__ void __launch_bounds__(256) k_scan1() {
    __shared__ int s[256];
    int b = blockIdx.x, t = threadIdx.x;
    int base = b * 1024 + t * 4;
    int v0 = g_deg[base], v1 = g_deg[base + 1], v2 = g_deg[base + 2], v3 = g_deg[base + 3];
    int s0 = v0, s1 = s0 + v1, s2 = s1 + v2, s3 = s2 + v3;
    s[t] = s3;
    __syncthreads();
    for (int off = 1; off < 256; off <<= 1) {
        int x = (t >= off) ? s[t - off] : 0;
        __syncthreads();
        if (t >= off) s[t] += x;
        __syncthreads();
    }
    int prev = (t > 0) ? s[t - 1] : 0;
    g_incl[base] = prev + s0; g_incl[base + 1] = prev + s1;
    g_incl[base + 2] = prev + s2; g_incl[base + 3] = prev + s3;
    if (t == 255) g_bsum[b] = s[255];
}
__global__ void __launch_bounds__(128) k_scan2() {
    __shared__ int s[128];
    int t = threadIdx.x;
    s[t] = (t < NBLK1) ? g_bsum[t] : 0;
    __syncthreads();
    for (int off = 1; off < 128; off <<= 1) {
        int x = (t >= off) ? s[t - off] : 0;
        __syncthreads();
        if (t >= off) s[t] += x;
        __syncthreads();
    }
    if (t < NBLK1) g_bsum[t] = (t > 0) ? s[t - 1] : 0;   // exclusive block offsets
}
__global__ void k_scan3() {
    int i = blockIdx.x * blockDim.x + threadIdx.x;
    if (i >= N_NODES) return;
    int st = g_incl[i] - g_deg[i] + g_bsum[i >> 10];
    g_start[i] = st;
    g_cur[i] = st;
}
__global__ void k_permute(const int* __restrict__ src, const int* __restrict__ dst) {
    int e = blockIdx.x * blockDim.x + threadIdx.x;
    if (e >= N_EDGES) return;
    int p = atomicAdd(&g_cur[dst[e]], 1);
    g_ssrc[p] = src[e];
}

// ---------------- gather: agg[d] = y[d] + sum_{e: dst=d} y[src[e]]  (pure fp32) ----------------
__global__ void __launch_bounds__(256) k_gather() {
    int d = blockIdx.x * 8 + (threadIdx.x >> 5);
    if (d >= N_NODES) return;
    int lane = threadIdx.x & 31;
    const float4* Y = (const float4*)g_y;
    float4 acc = Y[(size_t)d * 32 + lane];          // self term
    int s = g_start[d], n = g_deg[d];
    int e = s, end = s + n;
    for (; e + 4 <= end; e += 4) {
        int i0 = g_ssrc[e], i1 = g_ssrc[e + 1], i2 = g_ssrc[e + 2], i3 = g_ssrc[e + 3];
        float4 v0 = Y[(size_t)i0 * 32 + lane];
        float4 v1 = Y[(size_t)i1 * 32 + lane];
        float4 v2 = Y[(size_t)i2 * 32 + lane];
        float4 v3 = Y[(size_t)i3 * 32 + lane];
        acc.x += v0.x + v1.x + v2.x + v3.x;
        acc.y += v0.y + v1.y + v2.y + v3.y;
        acc.z += v0.z + v1.z + v2.z + v3.z;
        acc.w += v0.w + v1.w + v2.w + v3.w;
    }
    for (; e < end; e++) {
        int i0 = g_ssrc[e];
        float4 v0 = Y[(size_t)i0 * 32 + lane];
        acc.x += v0.x; acc.y += v0.y; acc.z += v0.z; acc.w += v0.w;
    }
    ((float4*)g_agg)[(size_t)d * 32 + lane] = acc;
}

// ---------------- persistent fused bf16x3 GEMM, M-tile 64, 512 threads, warp tile 16x32 ----------------
// MODE 0: A = x,                         epi: v = D + W1[z] + W1[100+z]; write y
// MODE 1: A = xs_prev*scale+shift (affine from raw stats), epi: v = D;  write y
// MODE 2: A = relu(agg + b1),            epi: v = relu(D + b2); write xs + BN stats
template <int MODE>
__global__ void __launch_bounds__(512, 2) k_mma(
    const float* __restrict__ A, int lda,
    const uint4* __restrict__ Wimg,
    const float* __restrict__ aux0,   // MODE1: gamma  MODE2: b1
    const float* __restrict__ aux1,   // MODE1: beta
    const int* __restrict__ z,        // MODE0
    const float* __restrict__ Wfull,  // MODE0: full W1_0
    const float* __restrict__ b2,     // MODE2
    float* __restrict__ out0, int ld0,
    int layer)
{
    extern __shared__ char smem[];
    __nv_bfloat16* sAh = (__nv_bfloat16*)smem;
    __nv_bfloat16* sAl = sAh + A64;
    __nv_bfloat16* sBh = sAl + A64;
    float* s_sum = (float*)(smem + (2 * A64 + 2 * B128) * 2);   // MODE2: stats  MODE1: scale
    float* s_sq  = s_sum + 128;                                 // MODE2: stats  MODE1: shift
    const int tid = threadIdx.x;
    const int wid = tid >> 5, lane = tid & 31;

    if (MODE == 2 && tid < 256) { s_sum[tid & 127] = 0.f; s_sq[tid & 127] = 0.f; }
    if (MODE == 1 && tid < 128) {
        const float invN = 1.0f / (float)N_NODES;
        int so = (layer - 1) * 128 + tid;
        float mu = g_sum[so] * invN;
        float var = g_sumsq[so] * invN - mu * mu;
        float s = aux0[tid] * rsqrtf(fmaxf(var, 0.f) + 1e-5f);
        s_sum[tid] = s;
        s_sq[tid] = aux1[tid] - mu * s;
    }

    // ---- copy pre-split B images ONCE (hi+lo = 4352 uint4) ----
    uint4* sB4 = (uint4*)sBh;
#pragma unroll
    for (int j = 0; j < 9; j++) {
        int idx = tid + j * 512;
        if (idx < 4352) sB4[idx] = Wimg[idx];
    }
    __syncthreads();   // B ready; MODE1 affine ready; MODE2 stats zeroed

    // fixed per-thread addressing
    const int wm = wid & 3, wn = wid >> 2;
    const int lr = lane >> 2, lq = lane & 3;
    const int lrow = lane & 7, lsel = lane >> 3;   // ldmatrix lane mapping
    const uint32_t sAh_u = (uint32_t)__cvta_generic_to_shared(sAh);
    const uint32_t sBh_u = (uint32_t)__cvta_generic_to_shared(sBh);
    const uint32_t loA = (uint32_t)(A64 * 2);     // bytes hi->lo (A)
    const uint32_t loB = (uint32_t)(B128 * 2);    // bytes hi->lo (B)
    uint32_t aBase;
    {
        int ar = wm * 16 + ((lsel & 1) << 3) + lrow;
        int ac = (lsel >> 1) << 3;
        aBase = sAh_u + (uint32_t)(ar * KP + ac) * 2;
    }
    uint32_t bBase[2];
#pragma unroll
    for (int p = 0; p < 2; p++) {
        int br = wn * 32 + p * 16 + ((lsel >> 1) << 3) + lrow;
        int bc = (lsel & 1) << 3;
        bBase[p] = sBh_u + (uint32_t)(br * KP + bc) * 2;
    }

    // ---- persistent loop over M-tiles ----
    for (int mb = blockIdx.x; mb < NB64; mb += GRID_MMA) {
        const int row0 = mb * 64;

        // ---- load A tile (64 rows) with fused transforms, split bf16 hi/lo ----
#pragma unroll
        for (int j = 0; j < 4; j++) {
            int v4 = tid + j * 512;
            int r = v4 >> 5, c4 = v4 & 31;
            int row = row0 + r;
            float4 a = make_float4(0.f, 0.f, 0.f, 0.f);
            if (row < N_NODES) {
                a = *(const float4*)(A + (size_t)row * lda + c4 * 4);
                if (MODE == 1) {
                    float4 sc = ((const float4*)s_sum)[c4];
                    float4 sh = ((const float4*)s_sq)[c4];
                    a.x = fmaf(a.x, sc.x, sh.x); a.y = fmaf(a.y, sc.y, sh.y);
                    a.z = fmaf(a.z, sc.z, sh.z); a.w = fmaf(a.w, sc.w, sh.w);
                } else if (MODE == 2) {
                    float4 bb = ((const float4*)aux0)[c4];
                    a.x = fmaxf(a.x + bb.x, 0.f); a.y = fmaxf(a.y + bb.y, 0.f);
                    a.z = fmaxf(a.z + bb.z, 0.f); a.w = fmaxf(a.w + bb.w, 0.f);
                }
            }
            __nv_bfloat16 h0 = __float2bfloat16(a.x), h1 = __float2bfloat16(a.y);
            __nv_bfloat16 h2 = __float2bfloat16(a.z), h3 = __float2bfloat16(a.w);
            __nv_bfloat16 l0 = __float2bfloat16(a.x - __bfloat162float(h0));
            __nv_bfloat16 l1 = __float2bfloat16(a.y - __bfloat162float(h1));
            __nv_bfloat16 l2 = __float2bfloat16(a.z - __bfloat162float(h2));
            __nv_bfloat16 l3 = __float2bfloat16(a.w - __bfloat162float(h3));
            *(uint2*)&sAh[r * KP + c4 * 4] = make_uint2(pack_bf2(h0, h1), pack_bf2(h2, h3));
            *(uint2*)&sAl[r * KP + c4 * 4] = make_uint2(pack_bf2(l0, l1), pack_bf2(l2, l3));
        }
        __syncthreads();

        // ---- mainloop ----
        float acc[4][4];
#pragma unroll
        for (int nb = 0; nb < 4; nb++)
#pragma unroll
            for (int i = 0; i < 4; i++) acc[nb][i] = 0.f;

#pragma unroll
        for (int ks = 0; ks < 8; ks++) {
            const uint32_t off = (uint32_t)ks * 32;    // 16 bf16 = 32 bytes per K step
            uint32_t ah[4], al[4], bh[2][4], bl[2][4];
            ldsm_x4(ah, aBase + off);
            ldsm_x4(al, aBase + off + loA);
#pragma unroll
            for (int p = 0; p < 2; p++) {
                ldsm_x4(bh[p], bBase[p] + off);
                ldsm_x4(bl[p], bBase[p] + off + loB);
            }
#pragma unroll
            for (int p = 0; p < 2; p++) {
                mma_bf16(acc[2 * p],     ah[0], ah[1], ah[2], ah[3], bh[p][0], bh[p][1]);
                mma_bf16(acc[2 * p],     al[0], al[1], al[2], al[3], bh[p][0], bh[p][1]);
                mma_bf16(acc[2 * p],     ah[0], ah[1], ah[2], ah[3], bl[p][0], bl[p][1]);
                mma_bf16(acc[2 * p + 1], ah[0], ah[1], ah[2], ah[3], bh[p][2], bh[p][3]);
                mma_bf16(acc[2 * p + 1], al[0], al[1], al[2], al[3], bh[p][2], bh[p][3]);
                mma_bf16(acc[2 * p + 1], ah[0], ah[1], ah[2], ah[3], bl[p][2], bl[p][3]);
            }
        }
        __syncthreads();   // all ldsm done before next tile overwrites A

        // ---- epilogue for this tile ----
        const int r0 = row0 + wm * 16 + lr;
        const int r1 = r0 + 8;
        int zi0 = 0, zi1 = 0;
        if (MODE == 0) {
            if (r0 < N_NODES) zi0 = z[r0];
            if (r1 < N_NODES) zi1 = z[r1];
        }
#pragma unroll
        for (int nb = 0; nb < 4; nb++) {
            const int c = wn * 32 + nb * 8 + 2 * lq;
            float2 v0 = make_float2(acc[nb][0], acc[nb][1]);
            float2 v1 = make_float2(acc[nb][2], acc[nb][3]);
            if (MODE == 0) {
                if (r0 < N_NODES) {
                    float2 e = *(const float2*)&Wfull[(size_t)zi0 * 128 + c];
                    float2 f = *(const float2*)&Wfull[(size_t)(100 + zi0) * 128 + c];
                    v0.x += e.x + f.x; v0.y += e.y + f.y;
                }
                if (r1 < N_NODES) {
                    float2 e = *(const float2*)&Wfull[(size_t)zi1 * 128 + c];
                    float2 f = *(const float2*)&Wfull[(size_t)(100 + zi1) * 128 + c];
                    v1.x += e.x + f.x; v1.y += e.y + f.y;
                }
            }
            if (MODE == 2) {
                float2 bb = *(const float2*)&b2[c];
                v0.x = fmaxf(v0.x + bb.x, 0.f); v0.y = fmaxf(v0.y + bb.y, 0.f);
                v1.x = fmaxf(v1.x + bb.x, 0.f); v1.y = fmaxf(v1.y + bb.y, 0.f);
            }
            float ps0 = 0.f, ps1 = 0.f, pq0 = 0.f, pq1 = 0.f;
            if (r0 < N_NODES) {
                *(float2*)&out0[(size_t)r0 * ld0 + c] = v0;
                if (MODE == 2) { ps0 += v0.x; ps1 += v0.y; pq0 += v0.x * v0.x; pq1 += v0.y * v0.y; }
            }
            if (r1 < N_NODES) {
                *(float2*)&out0[(size_t)r1 * ld0 + c] = v1;
                if (MODE == 2) { ps0 += v1.x; ps1 += v1.y; pq0 += v1.x * v1.x; pq1 += v1.y * v1.y; }
            }
            if (MODE == 2) {
                atomicAdd(&s_sum[c], ps0);
                atomicAdd(&s_sum[c + 1], ps1);
                atomicAdd(&s_sq[c], pq0);
                atomicAdd(&s_sq[c + 1], pq1);
            }
        }
    }

    if (MODE == 2) {
        __syncthreads();
        if (tid < 128) {
            atomicAdd(&g_sum[layer * 128 + tid], s_sum[tid]);
            atomicAdd(&g_sumsq[layer * 128 + tid], s_sq[tid]);
        }
    }
}

// ---------------- segmented pooling over SORTED batch ----------------
// Block = 128 consecutive nodes; thread t handles float4 column t (0..95).
// Registers accumulate per graph; RED flush only at graph boundaries.
__global__ void __launch_bounds__(96) k_pool2(const int* __restrict__ batch) {
    int r0 = blockIdx.x * 128;
    int t = threadIdx.x;
    __shared__ int sb[128];
    for (int i = t; i < 128; i += 96) {
        int r = r0 + i;
        sb[i] = (r < N_NODES) ? batch[r] : -1;
    }
    __syncthreads();
    float4 acc = make_float4(0.f, 0.f, 0.f, 0.f);
    int cur = sb[0];
    const float4* XS = (const float4*)g_xs;
    for (int i = 0; i < 128; i++) {
        int r = r0 + i;
        if (r >= N_NODES) break;
        int bb = sb[i];
        if (bb != cur) {
            red_add_v4(&g_pooled[(size_t)cur * XSD + t * 4], acc);
            acc = make_float4(0.f, 0.f, 0.f, 0.f);
            cur = bb;
        }
        float4 v = XS[(size_t)r * 96 + t];
        acc.x += v.x; acc.y += v.y; acc.z += v.z; acc.w += v.w;
    }
    if (cur >= 0) red_add_v4(&g_pooled[(size_t)cur * XSD + t * 4], acc);
}

// ---------------- final MLP (BN affine computed inline, folded into pooled sums) ----------------
__global__ void __launch_bounds__(128) k_mlp(
    const float* __restrict__ Wl1, const float* __restrict__ bl1,
    const float* __restrict__ Wl2, const float* __restrict__ bl2,
    const float* __restrict__ gam0, const float* __restrict__ bet0,
    const float* __restrict__ gam1, const float* __restrict__ bet1,
    const float* __restrict__ gam2, const float* __restrict__ bet2,
    float* __restrict__ out)
{
    int g = blockIdx.x;
    int c = threadIdx.x;
    __shared__ float sp[XSD];
    __shared__ float red[128];
    const float invN = 1.0f / (float)N_NODES;
    float cnt = (float)g_counts[g];
    float inv = 1.0f / fmaxf(cnt, 1.0f);
    for (int k = c; k < XSD; k += 128) {
        int l = k >> 7, ch = k & 127;
        const float* gm = l == 0 ? gam0 : l == 1 ? gam1 : gam2;
        const float* bt = l == 0 ? bet0 : l == 1 ? bet1 : bet2;
        float mu = g_sum[k] * invN;
        float var = g_sumsq[k] * invN - mu * mu;
        float s = gm[ch] * rsqrtf(fmaxf(var, 0.f) + 1e-5f);
        float sh = bt[ch] - mu * s;
        sp[k] = (g_pooled[(size_t)g * XSD + k] * s + cnt * sh) * inv;
    }
    __syncthreads();
    float acc = bl1[c];
    for (int k = 0; k < XSD; k++) acc += sp[k] * Wl1[(size_t)k * 128 + c];
    red[c] = fmaxf(acc, 0.f) * Wl2[c];
    __syncthreads();
    for (int s = 64; s > 0; s >>= 1) {
        if (c < s) red[c] += red[c + s];
        __syncthreads();
    }
    if (c == 0) out[g] = red[0] + bl2[0];
}

// ---------------- host ----------------
extern "C" void kernel_launch(void* const* d_in, const int* in_sizes, int n_in,
                              void* d_out, int out_size) {
    (void)in_sizes; (void)n_in; (void)out_size;
    const float* x     = (const float*)d_in[0];
    const int*   z     = (const int*)d_in[1];
    const int*   ei    = (const int*)d_in[2];
    const int*   batch = (const int*)d_in[3];
    const float *W1[3], *b1[3], *W2[3], *b2[3], *gam[3], *bet[3];
    for (int l = 0; l < 3; l++) {
        W1[l]  = (const float*)d_in[4 + 6 * l];
        b1[l]  = (const float*)d_in[5 + 6 * l];
        W2[l]  = (const float*)d_in[6 + 6 * l];
        b2[l]  = (const float*)d_in[7 + 6 * l];
        gam[l] = (const float*)d_in[8 + 6 * l];
        bet[l] = (const float*)d_in[9 + 6 * l];
    }
    const float* Wl1 = (const float*)d_in[22];
    const float* bl1 = (const float*)d_in[23];
    const float* Wl2 = (const float*)d_in[24];
    const float* bl2 = (const float*)d_in[25];
    const int* src = ei;
    const int* dst = ei + N_EDGES;

    void *yp, *aggp, *xsp, *wp;
    cudaGetSymbolAddress(&yp, g_y);
    cudaGetSymbolAddress(&aggp, g_agg);
    cudaGetSymbolAddress(&xsp, g_xs);
    cudaGetSymbolAddress(&wp, g_wimg);
    float* yb   = (float*)yp;
    float* aggb = (float*)aggp;
    float* xsb  = (float*)xsp;
    uint4* wimg = (uint4*)wp;

    cudaFuncSetAttribute(k_mma<0>, cudaFuncAttributeMaxDynamicSharedMemorySize, SMEM_BYTES);
    cudaFuncSetAttribute(k_mma<1>, cudaFuncAttributeMaxDynamicSharedMemorySize, SMEM_BYTES);
    cudaFuncSetAttribute(k_mma<2>, cudaFuncAttributeMaxDynamicSharedMemorySize, SMEM_BYTES);

    // launch order keeps k_mma<0> at capture index 3 for ncu
    k_prep<<<297, 256>>>(W1[0] + 200 * 128, W2[0], W1[1], W2[1], W1[2], W2[2]);   // 0
    k_hist<<<HIST_BLKS + 1, 256>>>(dst, batch);                                   // 1
    k_scan1<<<NBLK1, 256>>>();                                                    // 2
    k_mma<0><<<GRID_MMA, 512, SMEM_BYTES>>>(x, 128, wimg, nullptr, nullptr,
                                            z, W1[0], nullptr, yb, 128, 0);       // 3
    k_scan2<<<1, 128>>>();                                                        // 4
    k_scan3<<<(N_NODES + 255) / 256, 256>>>();                                    // 5
    k_permute<<<(N_EDGES + 255) / 256, 256>>>(src, dst);                          // 6

    for (int l = 0; l < 3; l++) {
        if (l > 0) {
            k_mma<1><<<GRID_MMA, 512, SMEM_BYTES>>>(xsb + (size_t)(l - 1) * 128, XSD,
                                                    wimg + (size_t)(2 * l) * 4352,
                                                    gam[l - 1], bet[l - 1],
                                                    nullptr, nullptr, nullptr, yb, 128, l);
        }
        k_gather<<<(N_NODES + 7) / 8, 256>>>();
        k_mma<2><<<GRID_MMA, 512, SMEM_BYTES>>>(aggb, 128, wimg + (size_t)(2 * l + 1) * 4352,
                                                b1[l], nullptr, nullptr, nullptr, b2[l],
                                                xsb + (size_t)l * 128, XSD, l);
    }

    k_pool2<<<(N_NODES + 127) / 128, 96>>>(batch);
    k_mlp<<<GG, 128>>>(Wl1, bl1, Wl2, bl2,
                       gam[0], bet[0], gam[1], bet[1], gam[2], bet[2],
                       (float*)d_out);
}

// round 15
// speedup vs baseline: 1.0429x; 1.0429x over previous
#include <cuda_runtime.h>
#include <cuda_bf16.h>
#include <cstdint>

#define N_NODES 100000
#define N_EDGES 1600000
#define HID 128
#define GG 512
#define XSD 384
#define NB64 1563                       // ceil(100000/64)
#define GRID_MMA 296                    // persistent: 2 CTAs/SM x 148 SMs
#define KP 136                          // smem pitch in bf16 elems
#define A64 (64 * KP)                   // elems per 64-row A image
#define B128 (128 * KP)                 // elems per 128-row B image
#define SMEM_BYTES ((2 * A64 + 2 * B128) * 2 + 1024)   // 105472
#define NBLK1 98                        // ceil(100000/1024)
#define HIST_BLKS 6250

// ---------------- scratch (static device globals; no allocation) ----------------
__device__ float g_y[N_NODES * HID];      // pre-aggregation features (gather source)
__device__ float g_agg[N_NODES * HID];    // self + edge aggregation
__device__ float g_xs[N_NODES * XSD];     // per-layer raw (pre-BN-affine) outputs
__device__ uint4 g_wimg[6 * 4352];        // 6 weights x (hi+lo) bf16 images [n][k] pitch KP
__device__ float g_pooled[GG * XSD];
__device__ float g_sum[3 * HID];
__device__ float g_sumsq[3 * HID];
__device__ int   g_counts[GG];
// CSR scratch
__device__ int g_deg[NBLK1 * 1024];
__device__ int g_incl[NBLK1 * 1024];
__device__ int g_start[N_NODES];
__device__ int g_cur[N_NODES];
__device__ int g_ssrc[N_EDGES];
__device__ int g_bsum[128];

// ---------------- helpers ----------------
__device__ __forceinline__ void red_add_v2(float* p, float2 v) {
    asm volatile("red.global.add.v2.f32 [%0], {%1, %2};"
                 :: "l"(p), "f"(v.x), "f"(v.y) : "memory");
}
__device__ __forceinline__ void mma_bf16(float* c, uint32_t a0, uint32_t a1, uint32_t a2,
                                         uint32_t a3, uint32_t b0, uint32_t b1) {
    asm volatile(
        "mma.sync.aligned.m16n8k16.row.col.f32.bf16.bf16.f32 "
        "{%0,%1,%2,%3}, {%4,%5,%6,%7}, {%8,%9}, {%0,%1,%2,%3};"
        : "+f"(c[0]), "+f"(c[1]), "+f"(c[2]), "+f"(c[3])
        : "r"(a0), "r"(a1), "r"(a2), "r"(a3), "r"(b0), "r"(b1));
}
__device__ __forceinline__ void ldsm_x4(uint32_t* r, uint32_t addr) {
    asm volatile("ldmatrix.sync.aligned.m8n8.x4.shared.b16 {%0,%1,%2,%3}, [%4];"
                 : "=r"(r[0]), "=r"(r[1]), "=r"(r[2]), "=r"(r[3]) : "r"(addr));
}
__device__ __forceinline__ uint32_t pack_bf2(__nv_bfloat16 lo, __nv_bfloat16 hi) {
    return (uint32_t)__bfloat16_as_ushort(lo) | ((uint32_t)__bfloat16_as_ushort(hi) << 16);
}

// ---------------- weight prep + stat/pool/deg zero ----------------
__global__ void k_prep(const float* __restrict__ w0, const float* __restrict__ w1,
                       const float* __restrict__ w2, const float* __restrict__ w3,
                       const float* __restrict__ w4, const float* __restrict__ w5) {
    int bb = blockIdx.x;
    if (bb < 6) {
        const float* W = bb == 0 ? w0 : bb == 1 ? w1 : bb == 2 ? w2 : bb == 3 ? w3 : bb == 4 ? w4 : w5;
        __nv_bfloat16* img = ((__nv_bfloat16*)g_wimg) + (size_t)bb * 2 * B128;
        for (int idx = threadIdx.x; idx < 16384; idx += 256) {
            int k = idx >> 7, n = idx & 127;
            float w = W[idx];
            __nv_bfloat16 h = __float2bfloat16(w);
            __nv_bfloat16 l = __float2bfloat16(w - __bfloat162float(h));
            img[n * KP + k] = h;
            img[B128 + n * KP + k] = l;
        }
    } else if (bb == 6) {
        for (int i = threadIdx.x; i < 3 * HID; i += 256) { g_sum[i] = 0.f; g_sumsq[i] = 0.f; }
    } else if (bb < 199) {
        int idx = (bb - 7) * 256 + threadIdx.x;
        if (idx < GG * XSD / 4) ((float4*)g_pooled)[idx] = make_float4(0.f, 0.f, 0.f, 0.f);
    } else {
        int base = (bb - 199) * 1024 + threadIdx.x * 4;
        *(int4*)&g_deg[base] = make_int4(0, 0, 0, 0);
    }
}

// ---------------- CSR hist + graph counts (merged) ----------------
__global__ void k_hist(const int* __restrict__ dst, const int* __restrict__ batch) {
    if (blockIdx.x < HIST_BLKS) {
        int e = blockIdx.x * 256 + threadIdx.x;
        if (e < N_EDGES) atomicAdd(&g_deg[dst[e]], 1);
    } else {
        __shared__ int h[GG];
        int t = threadIdx.x;
        for (int i = t; i < GG; i += 256) h[i] = 0;
        __syncthreads();
        for (int i = t; i < N_NODES; i += 256) atomicAdd(&h[batch[i]], 1);
        __syncthreads();
        for (int i = t; i < GG; i += 256) g_counts[i] = h[i];
    }
}

__global__ void __launch_bounds__(256) k_scan1() {
    __shared__ int s[256];
    int b = blockIdx.x, t = threadIdx.x;
    int base = b * 1024 + t * 4;
    int v0 = g_deg[base], v1 = g_deg[base + 1], v2 = g_deg[base + 2], v3 = g_deg[base + 3];
    int s0 = v0, s1 = s0 + v1, s2 = s1 + v2, s3 = s2 + v3;
    s[t] = s3;
    __syncthreads();
    for (int off = 1; off < 256; off <<= 1) {
        int x = (t >= off) ? s[t - off] : 0;
        __syncthreads();
        if (t >= off) s[t] += x;
        __syncthreads();
    }
    int prev = (t > 0) ? s[t - 1] : 0;
    g_incl[base] = prev + s0; g_incl[base + 1] = prev + s1;
    g_incl[base + 2] = prev + s2; g_incl[base + 3] = prev + s3;
    if (t == 255) g_bsum[b] = s[255];
}
__global__ void __launch_bounds__(128) k_scan2() {
    __shared__ int s[128];
    int t = threadIdx.x;
    s[t] = (t < NBLK1) ? g_bsum[t] : 0;
    __syncthreads();
    for (int off = 1; off < 128; off <<= 1) {
        int x = (t >= off) ? s[t - off] : 0;
        __syncthreads();
        if (t >= off) s[t] += x;
        __syncthreads();
    }
    if (t < NBLK1) g_bsum[t] = (t > 0) ? s[t - 1] : 0;   // exclusive block offsets
}
__global__ void k_scan3() {
    int i = blockIdx.x * blockDim.x + threadIdx.x;
    if (i >= N_NODES) return;
    int st = g_incl[i] - g_deg[i] + g_bsum[i >> 10];
    g_start[i] = st;
    g_cur[i] = st;
}
__global__ void k_permute(const int* __restrict__ src, const int* __restrict__ dst) {
    int e = blockIdx.x * blockDim.x + threadIdx.x;
    if (e >= N_EDGES) return;
    int p = atomicAdd(&g_cur[dst[e]], 1);
    g_ssrc[p] = src[e];
}

// ---------------- gather: agg[d] = y[d] + sum_{e: dst=d} y[src[e]]  (fp32, unroll 8) ----------------
__global__ void __launch_bounds__(256) k_gather() {
    int d = blockIdx.x * 8 + (threadIdx.x >> 5);
    if (d >= N_NODES) return;
    int lane = threadIdx.x & 31;
    const float4* Y = (const float4*)g_y;
    float4 acc = Y[(size_t)d * 32 + lane];          // self term
    float4 ac2 = make_float4(0.f, 0.f, 0.f, 0.f);
    int s = g_start[d], n = g_deg[d];
    int e = s, end = s + n;
    for (; e + 8 <= end; e += 8) {
        int i0 = g_ssrc[e],     i1 = g_ssrc[e + 1], i2 = g_ssrc[e + 2], i3 = g_ssrc[e + 3];
        int i4 = g_ssrc[e + 4], i5 = g_ssrc[e + 5], i6 = g_ssrc[e + 6], i7 = g_ssrc[e + 7];
        float4 v0 = Y[(size_t)i0 * 32 + lane];
        float4 v1 = Y[(size_t)i1 * 32 + lane];
        float4 v2 = Y[(size_t)i2 * 32 + lane];
        float4 v3 = Y[(size_t)i3 * 32 + lane];
        float4 v4 = Y[(size_t)i4 * 32 + lane];
        float4 v5 = Y[(size_t)i5 * 32 + lane];
        float4 v6 = Y[(size_t)i6 * 32 + lane];
        float4 v7 = Y[(size_t)i7 * 32 + lane];
        acc.x += v0.x + v1.x + v2.x + v3.x;
        acc.y += v0.y + v1.y + v2.y + v3.y;
        acc.z += v0.z + v1.z + v2.z + v3.z;
        acc.w += v0.w + v1.w + v2.w + v3.w;
        ac2.x += v4.x + v5.x + v6.x + v7.x;
        ac2.y += v4.y + v5.y + v6.y + v7.y;
        ac2.z += v4.z + v5.z + v6.z + v7.z;
        ac2.w += v4.w + v5.w + v6.w + v7.w;
    }
    for (; e + 4 <= end; e += 4) {
        int i0 = g_ssrc[e], i1 = g_ssrc[e + 1], i2 = g_ssrc[e + 2], i3 = g_ssrc[e + 3];
        float4 v0 = Y[(size_t)i0 * 32 + lane];
        float4 v1 = Y[(size_t)i1 * 32 + lane];
        float4 v2 = Y[(size_t)i2 * 32 + lane];
        float4 v3 = Y[(size_t)i3 * 32 + lane];
        acc.x += v0.x + v1.x + v2.x + v3.x;
        acc.y += v0.y + v1.y + v2.y + v3.y;
        acc.z += v0.z + v1.z + v2.z + v3.z;
        acc.w += v0.w + v1.w + v2.w + v3.w;
    }
    for (; e < end; e++) {
        int i0 = g_ssrc[e];
        float4 v0 = Y[(size_t)i0 * 32 + lane];
        acc.x += v0.x; acc.y += v0.y; acc.z += v0.z; acc.w += v0.w;
    }
    acc.x += ac2.x; acc.y += ac2.y; acc.z += ac2.z; acc.w += ac2.w;
    ((float4*)g_agg)[(size_t)d * 32 + lane] = acc;
}

// ---------------- persistent fused bf16x3 GEMM, M-tile 64, 512 threads, warp tile 16x32 ----------------
// MODE 0: A = x,                         epi: v = D + W1[z] + W1[100+z]; write y
// MODE 1: A = xs_prev*scale+shift (affine from raw stats), epi: v = D;  write y
// MODE 2: A = relu(agg + b1),            epi: v = relu(D + b2);
//         write xs (if write_xs) + BN stats + pooled red-add
template <int MODE>
__global__ void __launch_bounds__(512, 2) k_mma(
    const float* __restrict__ A, int lda,
    const uint4* __restrict__ Wimg,
    const float* __restrict__ aux0,   // MODE1: gamma  MODE2: b1
    const float* __restrict__ aux1,   // MODE1: beta
    const int* __restrict__ z,        // MODE0
    const float* __restrict__ Wfull,  // MODE0: full W1_0
    const float* __restrict__ b2,     // MODE2
    const int* __restrict__ batch,    // MODE2
    float* __restrict__ out0, int ld0,
    int layer, int write_xs)
{
    extern __shared__ char smem[];
    __nv_bfloat16* sAh = (__nv_bfloat16*)smem;
    __nv_bfloat16* sAl = sAh + A64;
    __nv_bfloat16* sBh = sAl + A64;
    float* s_sum = (float*)(smem + (2 * A64 + 2 * B128) * 2);   // MODE2: stats  MODE1: scale
    float* s_sq  = s_sum + 128;                                 // MODE2: stats  MODE1: shift
    const int tid = threadIdx.x;
    const int wid = tid >> 5, lane = tid & 31;

    if (MODE == 2 && tid < 256) { s_sum[tid & 127] = 0.f; s_sq[tid & 127] = 0.f; }
    if (MODE == 1 && tid < 128) {
        const float invN = 1.0f / (float)N_NODES;
        int so = (layer - 1) * 128 + tid;
        float mu = g_sum[so] * invN;
        float var = g_sumsq[so] * invN - mu * mu;
        float s = aux0[tid] * rsqrtf(fmaxf(var, 0.f) + 1e-5f);
        s_sum[tid] = s;
        s_sq[tid] = aux1[tid] - mu * s;
    }

    // ---- copy pre-split B images ONCE (hi+lo = 4352 uint4) ----
    uint4* sB4 = (uint4*)sBh;
#pragma unroll
    for (int j = 0; j < 9; j++) {
        int idx = tid + j * 512;
        if (idx < 4352) sB4[idx] = Wimg[idx];
    }
    __syncthreads();   // B ready; MODE1 affine ready; MODE2 stats zeroed

    // fixed per-thread addressing
    const int wm = wid & 3, wn = wid >> 2;
    const int lr = lane >> 2, lq = lane & 3;
    const int lrow = lane & 7, lsel = lane >> 3;   // ldmatrix lane mapping
    const uint32_t sAh_u = (uint32_t)__cvta_generic_to_shared(sAh);
    const uint32_t sBh_u = (uint32_t)__cvta_generic_to_shared(sBh);
    const uint32_t loA = (uint32_t)(A64 * 2);     // bytes hi->lo (A)
    const uint32_t loB = (uint32_t)(B128 * 2);    // bytes hi->lo (B)
    uint32_t aBase;
    {
        int ar = wm * 16 + ((lsel & 1) << 3) + lrow;
        int ac = (lsel >> 1) << 3;
        aBase = sAh_u + (uint32_t)(ar * KP + ac) * 2;
    }
    uint32_t bBase[2];
#pragma unroll
    for (int p = 0; p < 2; p++) {
        int br = wn * 32 + p * 16 + ((lsel >> 1) << 3) + lrow;
        int bc = (lsel & 1) << 3;
        bBase[p] = sBh_u + (uint32_t)(br * KP + bc) * 2;
    }

    // ---- persistent loop over M-tiles ----
    for (int mb = blockIdx.x; mb < NB64; mb += GRID_MMA) {
        const int row0 = mb * 64;

        // ---- load A tile (64 rows) with fused transforms, split bf16 hi/lo ----
#pragma unroll
        for (int j = 0; j < 4; j++) {
            int v4 = tid + j * 512;
            int r = v4 >> 5, c4 = v4 & 31;
            int row = row0 + r;
            float4 a = make_float4(0.f, 0.f, 0.f, 0.f);
            if (row < N_NODES) {
                a = *(const float4*)(A + (size_t)row * lda + c4 * 4);
                if (MODE == 1) {
                    float4 sc = ((const float4*)s_sum)[c4];
                    float4 sh = ((const float4*)s_sq)[c4];
                    a.x = fmaf(a.x, sc.x, sh.x); a.y = fmaf(a.y, sc.y, sh.y);
                    a.z = fmaf(a.z, sc.z, sh.z); a.w = fmaf(a.w, sc.w, sh.w);
                } else if (MODE == 2) {
                    float4 bb = ((const float4*)aux0)[c4];
                    a.x = fmaxf(a.x + bb.x, 0.f); a.y = fmaxf(a.y + bb.y, 0.f);
                    a.z = fmaxf(a.z + bb.z, 0.f); a.w = fmaxf(a.w + bb.w, 0.f);
                }
            }
            __nv_bfloat16 h0 = __float2bfloat16(a.x), h1 = __float2bfloat16(a.y);
            __nv_bfloat16 h2 = __float2bfloat16(a.z), h3 = __float2bfloat16(a.w);
            __nv_bfloat16 l0 = __float2bfloat16(a.x - __bfloat162float(h0));
            __nv_bfloat16 l1 = __float2bfloat16(a.y - __bfloat162float(h1));
            __nv_bfloat16 l2 = __float2bfloat16(a.z - __bfloat162float(h2));
            __nv_bfloat16 l3 = __float2bfloat16(a.w - __bfloat162float(h3));
            *(uint2*)&sAh[r * KP + c4 * 4] = make_uint2(pack_bf2(h0, h1), pack_bf2(h2, h3));
            *(uint2*)&sAl[r * KP + c4 * 4] = make_uint2(pack_bf2(l0, l1), pack_bf2(l2, l3));
        }
        __syncthreads();

        // ---- mainloop ----
        float acc[4][4];
#pragma unroll
        for (int nb = 0; nb < 4; nb++)
#pragma unroll
            for (int i = 0; i < 4; i++) acc[nb][i] = 0.f;

#pragma unroll
        for (int ks = 0; ks < 8; ks++) {
            const uint32_t off = (uint32_t)ks * 32;    // 16 bf16 = 32 bytes per K step
            uint32_t ah[4], al[4], bh[2][4], bl[2][4];
            ldsm_x4(ah, aBase + off);
            ldsm_x4(al, aBase + off + loA);
#pragma unroll
            for (int p = 0; p < 2; p++) {
                ldsm_x4(bh[p], bBase[p] + off);
                ldsm_x4(bl[p], bBase[p] + off + loB);
            }
#pragma unroll
            for (int p = 0; p < 2; p++) {
                mma_bf16(acc[2 * p],     ah[0], ah[1], ah[2], ah[3], bh[p][0], bh[p][1]);
                mma_bf16(acc[2 * p],     al[0], al[1], al[2], al[3], bh[p][0], bh[p][1]);
                mma_bf16(acc[2 * p],     ah[0], ah[1], ah[2], ah[3], bl[p][0], bl[p][1]);
                mma_bf16(acc[2 * p + 1], ah[0], ah[1], ah[2], ah[3], bh[p][2], bh[p][3]);
                mma_bf16(acc[2 * p + 1], al[0], al[1], al[2], al[3], bh[p][2], bh[p][3]);
                mma_bf16(acc[2 * p + 1], ah[0], ah[1], ah[2], ah[3], bl[p][2], bl[p][3]);
            }
        }
        __syncthreads();   // all ldsm done before next tile overwrites A

        // ---- epilogue for this tile ----
        const int r0 = row0 + wm * 16 + lr;
        const int r1 = r0 + 8;
        int zi0 = 0, zi1 = 0, bt0 = 0, bt1 = 0;
        if (MODE == 0) {
            if (r0 < N_NODES) zi0 = z[r0];
            if (r1 < N_NODES) zi1 = z[r1];
        }
        if (MODE == 2) {
            if (r0 < N_NODES) bt0 = batch[r0];
            if (r1 < N_NODES) bt1 = batch[r1];
        }
#pragma unroll
        for (int nb = 0; nb < 4; nb++) {
            const int c = wn * 32 + nb * 8 + 2 * lq;
            float2 v0 = make_float2(acc[nb][0], acc[nb][1]);
            float2 v1 = make_float2(acc[nb][2], acc[nb][3]);
            if (MODE == 0) {
                if (r0 < N_NODES) {
                    float2 e = *(const float2*)&Wfull[(size_t)zi0 * 128 + c];
                    float2 f = *(const float2*)&Wfull[(size_t)(100 + zi0) * 128 + c];
                    v0.x += e.x + f.x; v0.y += e.y + f.y;
                }
                if (r1 < N_NODES) {
                    float2 e = *(const float2*)&Wfull[(size_t)zi1 * 128 + c];
                    float2 f = *(const float2*)&Wfull[(size_t)(100 + zi1) * 128 + c];
                    v1.x += e.x + f.x; v1.y += e.y + f.y;
                }
            }
            if (MODE == 2) {
                float2 bb = *(const float2*)&b2[c];
                v0.x = fmaxf(v0.x + bb.x, 0.f); v0.y = fmaxf(v0.y + bb.y, 0.f);
                v1.x = fmaxf(v1.x + bb.x, 0.f); v1.y = fmaxf(v1.y + bb.y, 0.f);
            }
            float ps0 = 0.f, ps1 = 0.f, pq0 = 0.f, pq1 = 0.f;
            if (r0 < N_NODES) {
                if (MODE != 2) {
                    *(float2*)&out0[(size_t)r0 * ld0 + c] = v0;
                } else {
                    if (write_xs) *(float2*)&out0[(size_t)r0 * ld0 + c] = v0;
                    red_add_v2(&g_pooled[(size_t)bt0 * XSD + layer * 128 + c], v0);
                    ps0 += v0.x; ps1 += v0.y; pq0 += v0.x * v0.x; pq1 += v0.y * v0.y;
                }
            }
            if (r1 < N_NODES) {
                if (MODE != 2) {
                    *(float2*)&out0[(size_t)r1 * ld0 + c] = v1;
                } else {
                    if (write_xs) *(float2*)&out0[(size_t)r1 * ld0 + c] = v1;
                    red_add_v2(&g_pooled[(size_t)bt1 * XSD + layer * 128 + c], v1);
                    ps0 += v1.x; ps1 += v1.y; pq0 += v1.x * v1.x; pq1 += v1.y * v1.y;
                }
            }
            if (MODE == 2) {
                atomicAdd(&s_sum[c], ps0);
                atomicAdd(&s_sum[c + 1], ps1);
                atomicAdd(&s_sq[c], pq0);
                atomicAdd(&s_sq[c + 1], pq1);
            }
        }
    }

    if (MODE == 2) {
        __syncthreads();
        if (tid < 128) {
            atomicAdd(&g_sum[layer * 128 + tid], s_sum[tid]);
            atomicAdd(&g_sumsq[layer * 128 + tid], s_sq[tid]);
        }
    }
}

// ---------------- final MLP (BN affine computed inline, folded into pooled sums) ----------------
__global__ void __launch_bounds__(128) k_mlp(
    const float* __restrict__ Wl1, const float* __restrict__ bl1,
    const float* __restrict__ Wl2, const float* __restrict__ bl2,
    const float* __restrict__ gam0, const float* __restrict__ bet0,
    const float* __restrict__ gam1, const float* __restrict__ bet1,
    const float* __restrict__ gam2, const float* __restrict__ bet2,
    float* __restrict__ out)
{
    int g = blockIdx.x;
    int c = threadIdx.x;
    __shared__ float sp[XSD];
    __shared__ float red[128];
    const float invN = 1.0f / (float)N_NODES;
    float cnt = (float)g_counts[g];
    float inv = 1.0f / fmaxf(cnt, 1.0f);
    for (int k = c; k < XSD; k += 128) {
        int l = k >> 7, ch = k & 127;
        const float* gm = l == 0 ? gam0 : l == 1 ? gam1 : gam2;
        const float* bt = l == 0 ? bet0 : l == 1 ? bet1 : bet2;
        float mu = g_sum[k] * invN;
        float var = g_sumsq[k] * invN - mu * mu;
        float s = gm[ch] * rsqrtf(fmaxf(var, 0.f) + 1e-5f);
        float sh = bt[ch] - mu * s;
        sp[k] = (g_pooled[(size_t)g * XSD + k] * s + cnt * sh) * inv;
    }
    __syncthreads();
    float acc = bl1[c];
    for (int k = 0; k < XSD; k++) acc += sp[k] * Wl1[(size_t)k * 128 + c];
    red[c] = fmaxf(acc, 0.f) * Wl2[c];
    __syncthreads();
    for (int s = 64; s > 0; s >>= 1) {
        if (c < s) red[c] += red[c + s];
        __syncthreads();
    }
    if (c == 0) out[g] = red[0] + bl2[0];
}

// ---------------- host ----------------
extern "C" void kernel_launch(void* const* d_in, const int* in_sizes, int n_in,
                              void* d_out, int out_size) {
    (void)in_sizes; (void)n_in; (void)out_size;
    const float* x     = (const float*)d_in[0];
    const int*   z     = (const int*)d_in[1];
    const int*   ei    = (const int*)d_in[2];
    const int*   batch = (const int*)d_in[3];
    const float *W1[3], *b1[3], *W2[3], *b2[3], *gam[3], *bet[3];
    for (int l = 0; l < 3; l++) {
        W1[l]  = (const float*)d_in[4 + 6 * l];
        b1[l]  = (const float*)d_in[5 + 6 * l];
        W2[l]  = (const float*)d_in[6 + 6 * l];
        b2[l]  = (const float*)d_in[7 + 6 * l];
        gam[l] = (const float*)d_in[8 + 6 * l];
        bet[l] = (const float*)d_in[9 + 6 * l];
    }
    const float* Wl1 = (const float*)d_in[22];
    const float* bl1 = (const float*)d_in[23];
    const float* Wl2 = (const float*)d_in[24];
    const float* bl2 = (const float*)d_in[25];
    const int* src = ei;
    const int* dst = ei + N_EDGES;

    void *yp, *aggp, *xsp, *wp;
    cudaGetSymbolAddress(&yp, g_y);
    cudaGetSymbolAddress(&aggp, g_agg);
    cudaGetSymbolAddress(&xsp, g_xs);
    cudaGetSymbolAddress(&wp, g_wimg);
    float* yb   = (float*)yp;
    float* aggb = (float*)aggp;
    float* xsb  = (float*)xsp;
    uint4* wimg = (uint4*)wp;

    cudaFuncSetAttribute(k_mma<0>, cudaFuncAttributeMaxDynamicSharedMemorySize, SMEM_BYTES);
    cudaFuncSetAttribute(k_mma<1>, cudaFuncAttributeMaxDynamicSharedMemorySize, SMEM_BYTES);
    cudaFuncSetAttribute(k_mma<2>, cudaFuncAttributeMaxDynamicSharedMemorySize, SMEM_BYTES);

    // launch order keeps k_mma<0> at capture index 3 for ncu
    k_prep<<<297, 256>>>(W1[0] + 200 * 128, W2[0], W1[1], W2[1], W1[2], W2[2]);   // 0
    k_hist<<<HIST_BLKS + 1, 256>>>(dst, batch);                                   // 1
    k_scan1<<<NBLK1, 256>>>();                                                    // 2
    k_mma<0><<<GRID_MMA, 512, SMEM_BYTES>>>(x, 128, wimg, nullptr, nullptr,
                                            z, W1[0], nullptr, nullptr, yb, 128, 0, 1); // 3
    k_scan2<<<1, 128>>>();                                                        // 4
    k_scan3<<<(N_NODES + 255) / 256, 256>>>();                                    // 5
    k_permute<<<(N_EDGES + 255) / 256, 256>>>(src, dst);                          // 6

    for (int l = 0; l < 3; l++) {
        if (l > 0) {
            k_mma<1><<<GRID_MMA, 512, SMEM_BYTES>>>(xsb + (size_t)(l - 1) * 128, XSD,
                                                    wimg + (size_t)(2 * l) * 4352,
                                                    gam[l - 1], bet[l - 1],
                                                    nullptr, nullptr, nullptr, nullptr, yb, 128, l, 1);
        }
        k_gather<<<(N_NODES + 7) / 8, 256>>>();
        k_mma<2><<<GRID_MMA, 512, SMEM_BYTES>>>(aggb, 128, wimg + (size_t)(2 * l + 1) * 4352,
                                                b1[l], nullptr, nullptr, nullptr, b2[l], batch,
                                                xsb + (size_t)l * 128, XSD, l, l < 2 ? 1 : 0);
    }

    k_mlp<<<GG, 128>>>(Wl1, bl1, Wl2, bl2,
                       gam[0], bet[0], gam[1], bet[1], gam[2], bet[2],
                       (float*)d_out);
}

// round 16
// speedup vs baseline: 1.0957x; 1.0506x over previous
#include <cuda_runtime.h>
#include <cuda_bf16.h>
#include <cstdint>

#define N_NODES 100000
#define N_EDGES 1600000
#define HID 128
#define GG 512
#define XSD 384
#define NB64 1563                       // ceil(100000/64)
#define GRID_MMA 296                    // persistent: 2 CTAs/SM x 148 SMs
#define KP 136                          // smem pitch in bf16 elems
#define A64 (64 * KP)                   // elems per 64-row A image
#define B128 (128 * KP)                 // elems per 128-row B image
#define SMEM_BYTES ((2 * A64 + 2 * B128) * 2 + 1024)   // 105472
#define NBLK1 98                        // ceil(100000/1024)

// ---------------- scratch (static device globals; no allocation) ----------------
__device__ float g_y[N_NODES * HID];      // pre-aggregation features (gather source)
__device__ float g_agg[N_NODES * HID];    // self + edge aggregation
__device__ float g_xs[N_NODES * XSD];     // per-layer raw (pre-BN-affine) outputs
__device__ uint4 g_wimg[6 * 4352];        // 6 weights x (hi+lo) bf16 images [n][k] pitch KP
__device__ float g_pooled[GG * XSD];
__device__ float g_sum[3 * HID];
__device__ float g_sumsq[3 * HID];
__device__ int   g_counts[GG];
// CSR scratch
__device__ int g_deg[NBLK1 * 1024];
__device__ int g_incl[NBLK1 * 1024];
__device__ int g_start[N_NODES];
__device__ int g_cur[N_NODES];
__device__ int g_ssrc[N_EDGES];
__device__ int g_bsum[128];

// ---------------- helpers ----------------
__device__ __forceinline__ void red_add_v2(float* p, float2 v) {
    asm volatile("red.global.add.v2.f32 [%0], {%1, %2};"
                 :: "l"(p), "f"(v.x), "f"(v.y) : "memory");
}
__device__ __forceinline__ void mma_bf16(float* c, uint32_t a0, uint32_t a1, uint32_t a2,
                                         uint32_t a3, uint32_t b0, uint32_t b1) {
    asm volatile(
        "mma.sync.aligned.m16n8k16.row.col.f32.bf16.bf16.f32 "
        "{%0,%1,%2,%3}, {%4,%5,%6,%7}, {%8,%9}, {%0,%1,%2,%3};"
        : "+f"(c[0]), "+f"(c[1]), "+f"(c[2]), "+f"(c[3])
        : "r"(a0), "r"(a1), "r"(a2), "r"(a3), "r"(b0), "r"(b1));
}
__device__ __forceinline__ void ldsm_x4(uint32_t* r, uint32_t addr) {
    asm volatile("ldmatrix.sync.aligned.m8n8.x4.shared.b16 {%0,%1,%2,%3}, [%4];"
                 : "=r"(r[0]), "=r"(r[1]), "=r"(r[2]), "=r"(r[3]) : "r"(addr));
}
__device__ __forceinline__ uint32_t pack_bf2(__nv_bfloat16 lo, __nv_bfloat16 hi) {
    return (uint32_t)__bfloat16_as_ushort(lo) | ((uint32_t)__bfloat16_as_ushort(hi) << 16);
}

// ---------------- weight prep + stat/pool/deg zero ----------------
__global__ void k_prep(const float* __restrict__ w0, const float* __restrict__ w1,
                       const float* __restrict__ w2, const float* __restrict__ w3,
                       const float* __restrict__ w4, const float* __restrict__ w5) {
    int bb = blockIdx.x;
    if (bb < 6) {
        const float* W = bb == 0 ? w0 : bb == 1 ? w1 : bb == 2 ? w2 : bb == 3 ? w3 : bb == 4 ? w4 : w5;
        __nv_bfloat16* img = ((__nv_bfloat16*)g_wimg) + (size_t)bb * 2 * B128;
        for (int idx = threadIdx.x; idx < 16384; idx += 256) {
            int k = idx >> 7, n = idx & 127;
            float w = W[idx];
            __nv_bfloat16 h = __float2bfloat16(w);
            __nv_bfloat16 l = __float2bfloat16(w - __bfloat162float(h));
            img[n * KP + k] = h;
            img[B128 + n * KP + k] = l;
        }
    } else if (bb == 6) {
        for (int i = threadIdx.x; i < 3 * HID; i += 256) { g_sum[i] = 0.f; g_sumsq[i] = 0.f; }
    } else if (bb < 199) {
        int idx = (bb - 7) * 256 + threadIdx.x;
        if (idx < GG * XSD / 4) ((float4*)g_pooled)[idx] = make_float4(0.f, 0.f, 0.f, 0.f);
    } else {
        int base = (bb - 199) * 1024 + threadIdx.x * 4;
        *(int4*)&g_deg[base] = make_int4(0, 0, 0, 0);
    }
}

// ---------------- CSR hist ----------------
__global__ void k_hist(const int* __restrict__ dst, const int* __restrict__ batch) {
    if (blockIdx.x < 6250) {
        int e = blockIdx.x * 256 + threadIdx.x;
        if (e < N_EDGES) atomicAdd(&g_deg[dst[e]], 1);
    } else {
        __shared__ int h[GG];
        int t = threadIdx.x;
        for (int i = t; i < GG; i += 256) h[i] = 0;
        __syncthreads();
        for (int i = t; i < N_NODES; i += 256) atomicAdd(&h[batch[i]], 1);
        __syncthreads();
        for (int i = t; i < GG; i += 256) g_counts[i] = h[i];
    }
}

__global__ void __launch_bounds__(256) k_scan1() {
    __shared__ int s[256];
    int b = blockIdx.x, t = threadIdx.x;
    int base = b * 1024 + t * 4;
    int v0 = g_deg[base], v1 = g_deg[base + 1], v2 = g_deg[base + 2], v3 = g_deg[base + 3];
    int s0 = v0, s1 = s0 + v1, s2 = s1 + v2, s3 = s2 + v3;
    s[t] = s3;
    __syncthreads();
    for (int off = 1; off < 256; off <<= 1) {
        int x = (t >= off) ? s[t - off] : 0;
        __syncthreads();
        if (t >= off) s[t] += x;
        __syncthreads();
    }
    int prev = (t > 0) ? s[t - 1] : 0;
    g_incl[base] = prev + s0; g_incl[base + 1] = prev + s1;
    g_incl[base + 2] = prev + s2; g_incl[base + 3] = prev + s3;
    if (t == 255) g_bsum[b] = s[255];
}
__global__ void __launch_bounds__(128) k_scan2() {
    __shared__ int s[128];
    int t = threadIdx.x;
    s[t] = (t < NBLK1) ? g_bsum[t] : 0;
    __syncthreads();
    for (int off = 1; off < 128; off <<= 1) {
        int x = (t >= off) ? s[t - off] : 0;
        __syncthreads();
        if (t >= off) s[t] += x;
        __syncthreads();
    }
    if (t < NBLK1) g_bsum[t] = (t > 0) ? s[t - 1] : 0;   // exclusive block offsets
}
__global__ void k_scan3() {
    int i = blockIdx.x * blockDim.x + threadIdx.x;
    if (i >= N_NODES) return;
    int st = g_incl[i] - g_deg[i] + g_bsum[i >> 10];
    g_start[i] = st;
    g_cur[i] = st;
}
__global__ void k_permute(const int* __restrict__ src, const int* __restrict__ dst) {
    int e = blockIdx.x * blockDim.x + threadIdx.x;
    if (e >= N_EDGES) return;
    int p = atomicAdd(&g_cur[dst[e]], 1);
    g_ssrc[p] = src[e];
}

// ---------------- gather: agg[d] = y[d] + sum_{e: dst=d} y[src[e]]  (fp32, unroll 4) ----------------
__global__ void __launch_bounds__(256) k_gather() {
    int d = blockIdx.x * 8 + (threadIdx.x >> 5);
    if (d >= N_NODES) return;
    int lane = threadIdx.x & 31;
    const float4* Y = (const float4*)g_y;
    float4 acc = Y[(size_t)d * 32 + lane];          // self term
    int s = g_start[d], n = g_deg[d];
    int e = s, end = s + n;
    for (; e + 4 <= end; e += 4) {
        int i0 = g_ssrc[e], i1 = g_ssrc[e + 1], i2 = g_ssrc[e + 2], i3 = g_ssrc[e + 3];
        float4 v0 = Y[(size_t)i0 * 32 + lane];
        float4 v1 = Y[(size_t)i1 * 32 + lane];
        float4 v2 = Y[(size_t)i2 * 32 + lane];
        float4 v3 = Y[(size_t)i3 * 32 + lane];
        acc.x += v0.x + v1.x + v2.x + v3.x;
        acc.y += v0.y + v1.y + v2.y + v3.y;
        acc.z += v0.z + v1.z + v2.z + v3.z;
        acc.w += v0.w + v1.w + v2.w + v3.w;
    }
    for (; e < end; e++) {
        int i0 = g_ssrc[e];
        float4 v0 = Y[(size_t)i0 * 32 + lane];
        acc.x += v0.x; acc.y += v0.y; acc.z += v0.z; acc.w += v0.w;
    }
    ((float4*)g_agg)[(size_t)d * 32 + lane] = acc;
}

// ---------------- persistent fused bf16x3 GEMM, M-tile 64, 512 threads, warp tile 16x32 ----------------
// MODE 0: A = x,                         epi: v = D + W1[z] + W1[100+z]; write y
// MODE 1: A = xs_prev*scale+shift (affine from raw stats), epi: v = D;  write y
// MODE 2: A = relu(agg + b1),            epi: v = relu(D + b2);
//         write xs (if write_xs) + BN stats + pooled red-add
template <int MODE>
__global__ void __launch_bounds__(512, 2) k_mma(
    const float* __restrict__ A, int lda,
    const uint4* __restrict__ Wimg,
    const float* __restrict__ aux0,   // MODE1: gamma  MODE2: b1
    const float* __restrict__ aux1,   // MODE1: beta
    const int* __restrict__ z,        // MODE0
    const float* __restrict__ Wfull,  // MODE0: full W1_0
    const float* __restrict__ b2,     // MODE2
    const int* __restrict__ batch,    // MODE2
    float* __restrict__ out0, int ld0,
    int layer, int write_xs)
{
    extern __shared__ char smem[];
    __nv_bfloat16* sAh = (__nv_bfloat16*)smem;
    __nv_bfloat16* sAl = sAh + A64;
    __nv_bfloat16* sBh = sAl + A64;
    float* s_sum = (float*)(smem + (2 * A64 + 2 * B128) * 2);   // MODE2: stats  MODE1: scale
    float* s_sq  = s_sum + 128;                                 // MODE2: stats  MODE1: shift
    const int tid = threadIdx.x;
    const int wid = tid >> 5, lane = tid & 31;

    if (MODE == 2 && tid < 256) { s_sum[tid & 127] = 0.f; s_sq[tid & 127] = 0.f; }
    if (MODE == 1 && tid < 128) {
        const float invN = 1.0f / (float)N_NODES;
        int so = (layer - 1) * 128 + tid;
        float mu = g_sum[so] * invN;
        float var = g_sumsq[so] * invN - mu * mu;
        float s = aux0[tid] * rsqrtf(fmaxf(var, 0.f) + 1e-5f);
        s_sum[tid] = s;
        s_sq[tid] = aux1[tid] - mu * s;
    }

    // ---- copy pre-split B images ONCE (hi+lo = 4352 uint4) ----
    uint4* sB4 = (uint4*)sBh;
#pragma unroll
    for (int j = 0; j < 9; j++) {
        int idx = tid + j * 512;
        if (idx < 4352) sB4[idx] = Wimg[idx];
    }
    __syncthreads();   // B ready; MODE1 affine ready; MODE2 stats zeroed

    // fixed per-thread addressing
    const int wm = wid & 3, wn = wid >> 2;
    const int lr = lane >> 2, lq = lane & 3;
    const int lrow = lane & 7, lsel = lane >> 3;   // ldmatrix lane mapping
    const uint32_t sAh_u = (uint32_t)__cvta_generic_to_shared(sAh);
    const uint32_t sBh_u = (uint32_t)__cvta_generic_to_shared(sBh);
    const uint32_t loA = (uint32_t)(A64 * 2);     // bytes hi->lo (A)
    const uint32_t loB = (uint32_t)(B128 * 2);    // bytes hi->lo (B)
    uint32_t aBase;
    {
        int ar = wm * 16 + ((lsel & 1) << 3) + lrow;
        int ac = (lsel >> 1) << 3;
        aBase = sAh_u + (uint32_t)(ar * KP + ac) * 2;
    }
    uint32_t bBase[2];
#pragma unroll
    for (int p = 0; p < 2; p++) {
        int br = wn * 32 + p * 16 + ((lsel >> 1) << 3) + lrow;
        int bc = (lsel & 1) << 3;
        bBase[p] = sBh_u + (uint32_t)(br * KP + bc) * 2;
    }

    // ---- persistent loop over M-tiles ----
    for (int mb = blockIdx.x; mb < NB64; mb += GRID_MMA) {
        const int row0 = mb * 64;

        // ---- load A tile (64 rows) with fused transforms, split bf16 hi/lo ----
#pragma unroll
        for (int j = 0; j < 4; j++) {
            int v4 = tid + j * 512;
            int r = v4 >> 5, c4 = v4 & 31;
            int row = row0 + r;
            float4 a = make_float4(0.f, 0.f, 0.f, 0.f);
            if (row < N_NODES) {
                a = *(const float4*)(A + (size_t)row * lda + c4 * 4);
                if (MODE == 1) {
                    float4 sc = ((const float4*)s_sum)[c4];
                    float4 sh = ((const float4*)s_sq)[c4];
                    a.x = fmaf(a.x, sc.x, sh.x); a.y = fmaf(a.y, sc.y, sh.y);
                    a.z = fmaf(a.z, sc.z, sh.z); a.w = fmaf(a.w, sc.w, sh.w);
                } else if (MODE == 2) {
                    float4 bb = ((const float4*)aux0)[c4];
                    a.x = fmaxf(a.x + bb.x, 0.f); a.y = fmaxf(a.y + bb.y, 0.f);
                    a.z = fmaxf(a.z + bb.z, 0.f); a.w = fmaxf(a.w + bb.w, 0.f);
                }
            }
            __nv_bfloat16 h0 = __float2bfloat16(a.x), h1 = __float2bfloat16(a.y);
            __nv_bfloat16 h2 = __float2bfloat16(a.z), h3 = __float2bfloat16(a.w);
            __nv_bfloat16 l0 = __float2bfloat16(a.x - __bfloat162float(h0));
            __nv_bfloat16 l1 = __float2bfloat16(a.y - __bfloat162float(h1));
            __nv_bfloat16 l2 = __float2bfloat16(a.z - __bfloat162float(h2));
            __nv_bfloat16 l3 = __float2bfloat16(a.w - __bfloat162float(h3));
            *(uint2*)&sAh[r * KP + c4 * 4] = make_uint2(pack_bf2(h0, h1), pack_bf2(h2, h3));
            *(uint2*)&sAl[r * KP + c4 * 4] = make_uint2(pack_bf2(l0, l1), pack_bf2(l2, l3));
        }
        __syncthreads();

        // ---- mainloop ----
        float acc[4][4];
#pragma unroll
        for (int nb = 0; nb < 4; nb++)
#pragma unroll
            for (int i = 0; i < 4; i++) acc[nb][i] = 0.f;

#pragma unroll
        for (int ks = 0; ks < 8; ks++) {
            const uint32_t off = (uint32_t)ks * 32;    // 16 bf16 = 32 bytes per K step
            uint32_t ah[4], al[4], bh[2][4], bl[2][4];
            ldsm_x4(ah, aBase + off);
            ldsm_x4(al, aBase + off + loA);
#pragma unroll
            for (int p = 0; p < 2; p++) {
                ldsm_x4(bh[p], bBase[p] + off);
                ldsm_x4(bl[p], bBase[p] + off + loB);
            }
#pragma unroll
            for (int p = 0; p < 2; p++) {
                mma_bf16(acc[2 * p],     ah[0], ah[1], ah[2], ah[3], bh[p][0], bh[p][1]);
                mma_bf16(acc[2 * p],     al[0], al[1], al[2], al[3], bh[p][0], bh[p][1]);
                mma_bf16(acc[2 * p],     ah[0], ah[1], ah[2], ah[3], bl[p][0], bl[p][1]);
                mma_bf16(acc[2 * p + 1], ah[0], ah[1], ah[2], ah[3], bh[p][2], bh[p][3]);
                mma_bf16(acc[2 * p + 1], al[0], al[1], al[2], al[3], bh[p][2], bh[p][3]);
                mma_bf16(acc[2 * p + 1], ah[0], ah[1], ah[2], ah[3], bl[p][2], bl[p][3]);
            }
        }
        __syncthreads();   // all ldsm done before next tile overwrites A

        // ---- epilogue for this tile ----
        const int r0 = row0 + wm * 16 + lr;
        const int r1 = r0 + 8;
        int zi0 = 0, zi1 = 0, bt0 = 0, bt1 = 0;
        if (MODE == 0) {
            if (r0 < N_NODES) zi0 = z[r0];
            if (r1 < N_NODES) zi1 = z[r1];
        }
        if (MODE == 2) {
            if (r0 < N_NODES) bt0 = batch[r0];
            if (r1 < N_NODES) bt1 = batch[r1];
        }
#pragma unroll
        for (int nb = 0; nb < 4; nb++) {
            const int c = wn * 32 + nb * 8 + 2 * lq;
            float2 v0 = make_float2(acc[nb][0], acc[nb][1]);
            float2 v1 = make_float2(acc[nb][2], acc[nb][3]);
            if (MODE == 0) {
                if (r0 < N_NODES) {
                    float2 e = *(const float2*)&Wfull[(size_t)zi0 * 128 + c];
                    float2 f = *(const float2*)&Wfull[(size_t)(100 + zi0) * 128 + c];
                    v0.x += e.x + f.x; v0.y += e.y + f.y;
                }
                if (r1 < N_NODES) {
                    float2 e = *(const float2*)&Wfull[(size_t)zi1 * 128 + c];
                    float2 f = *(const float2*)&Wfull[(size_t)(100 + zi1) * 128 + c];
                    v1.x += e.x + f.x; v1.y += e.y + f.y;
                }
            }
            if (MODE == 2) {
                float2 bb = *(const float2*)&b2[c];
                v0.x = fmaxf(v0.x + bb.x, 0.f); v0.y = fmaxf(v0.y + bb.y, 0.f);
                v1.x = fmaxf(v1.x + bb.x, 0.f); v1.y = fmaxf(v1.y + bb.y, 0.f);
            }
            float ps0 = 0.f, ps1 = 0.f, pq0 = 0.f, pq1 = 0.f;
            if (r0 < N_NODES) {
                if (MODE != 2) {
                    *(float2*)&out0[(size_t)r0 * ld0 + c] = v0;
                } else {
                    if (write_xs) *(float2*)&out0[(size_t)r0 * ld0 + c] = v0;
                    red_add_v2(&g_pooled[(size_t)bt0 * XSD + layer * 128 + c], v0);
                    ps0 += v0.x; ps1 += v0.y; pq0 += v0.x * v0.x; pq1 += v0.y * v0.y;
                }
            }
            if (r1 < N_NODES) {
                if (MODE != 2) {
                    *(float2*)&out0[(size_t)r1 * ld0 + c] = v1;
                } else {
                    if (write_xs) *(float2*)&out0[(size_t)r1 * ld0 + c] = v1;
                    red_add_v2(&g_pooled[(size_t)bt1 * XSD + layer * 128 + c], v1);
                    ps0 += v1.x; ps1 += v1.y; pq0 += v1.x * v1.x; pq1 += v1.y * v1.y;
                }
            }
            if (MODE == 2) {
                atomicAdd(&s_sum[c], ps0);
                atomicAdd(&s_sum[c + 1], ps1);
                atomicAdd(&s_sq[c], pq0);
                atomicAdd(&s_sq[c + 1], pq1);
            }
        }
    }

    if (MODE == 2) {
        __syncthreads();
        if (tid < 128) {
            atomicAdd(&g_sum[layer * 128 + tid], s_sum[tid]);
            atomicAdd(&g_sumsq[layer * 128 + tid], s_sq[tid]);
        }
    }
}

// ---------------- final MLP (BN affine computed inline, folded into pooled sums) ----------------
__global__ void __launch_bounds__(128) k_mlp(
    const float* __restrict__ Wl1, const float* __restrict__ bl1,
    const float* __restrict__ Wl2, const float* __restrict__ bl2,
    const float* __restrict__ gam0, const float* __restrict__ bet0,
    const float* __restrict__ gam1, const float* __restrict__ bet1,
    const float* __restrict__ gam2, const float* __restrict__ bet2,
    float* __restrict__ out)
{
    int g = blockIdx.x;
    int c = threadIdx.x;
    __shared__ float sp[XSD];
    __shared__ float red[128];
    const float invN = 1.0f / (float)N_NODES;
    float cnt = (float)g_counts[g];
    float inv = 1.0f / fmaxf(cnt, 1.0f);
    for (int k = c; k < XSD; k += 128) {
        int l = k >> 7, ch = k & 127;
        const float* gm = l == 0 ? gam0 : l == 1 ? gam1 : gam2;
        const float* bt = l == 0 ? bet0 : l == 1 ? bet1 : bet2;
        float mu = g_sum[k] * invN;
        float var = g_sumsq[k] * invN - mu * mu;
        float s = gm[ch] * rsqrtf(fmaxf(var, 0.f) + 1e-5f);
        float sh = bt[ch] - mu * s;
        sp[k] = (g_pooled[(size_t)g * XSD + k] * s + cnt * sh) * inv;
    }
    __syncthreads();
    float acc = bl1[c];
    for (int k = 0; k < XSD; k++) acc += sp[k] * Wl1[(size_t)k * 128 + c];
    red[c] = fmaxf(acc, 0.f) * Wl2[c];
    __syncthreads();
    for (int s = 64; s > 0; s >>= 1) {
        if (c < s) red[c] += red[c + s];
        __syncthreads();
    }
    if (c == 0) out[g] = red[0] + bl2[0];
}

// ---------------- host ----------------
extern "C" void kernel_launch(void* const* d_in, const int* in_sizes, int n_in,
                              void* d_out, int out_size) {
    (void)in_sizes; (void)n_in; (void)out_size;
    const float* x     = (const float*)d_in[0];
    const int*   z     = (const int*)d_in[1];
    const int*   ei    = (const int*)d_in[2];
    const int*   batch = (const int*)d_in[3];
    const float *W1[3], *b1[3], *W2[3], *b2[3], *gam[3], *bet[3];
    for (int l = 0; l < 3; l++) {
        W1[l]  = (const float*)d_in[4 + 6 * l];
        b1[l]  = (const float*)d_in[5 + 6 * l];
        W2[l]  = (const float*)d_in[6 + 6 * l];
        b2[l]  = (const float*)d_in[7 + 6 * l];
        gam[l] = (const float*)d_in[8 + 6 * l];
        bet[l] = (const float*)d_in[9 + 6 * l];
    }
    const float* Wl1 = (const float*)d_in[22];
    const float* bl1 = (const float*)d_in[23];
    const float* Wl2 = (const float*)d_in[24];
    const float* bl2 = (const float*)d_in[25];
    const int* src = ei;
    const int* dst = ei + N_EDGES;

    void *yp, *aggp, *xsp, *wp;
    cudaGetSymbolAddress(&yp, g_y);
    cudaGetSymbolAddress(&aggp, g_agg);
    cudaGetSymbolAddress(&xsp, g_xs);
    cudaGetSymbolAddress(&wp, g_wimg);
    float* yb   = (float*)yp;
    float* aggb = (float*)aggp;
    float* xsb  = (float*)xsp;
    uint4* wimg = (uint4*)wp;

    cudaFuncSetAttribute(k_mma<0>, cudaFuncAttributeMaxDynamicSharedMemorySize, SMEM_BYTES);
    cudaFuncSetAttribute(k_mma<1>, cudaFuncAttributeMaxDynamicSharedMemorySize, SMEM_BYTES);
    cudaFuncSetAttribute(k_mma<2>, cudaFuncAttributeMaxDynamicSharedMemorySize, SMEM_BYTES);

    // launch order keeps k_mma<0> at capture index 3 for ncu
    k_prep<<<297, 256>>>(W1[0] + 200 * 128, W2[0], W1[1], W2[1], W1[2], W2[2]);   // 0
    k_hist<<<6251, 256>>>(dst, batch);                                            // 1
    k_scan1<<<NBLK1, 256>>>();                                                    // 2
    k_mma<0><<<GRID_MMA, 512, SMEM_BYTES>>>(x, 128, wimg, nullptr, nullptr,
                                            z, W1[0], nullptr, nullptr, yb, 128, 0, 1); // 3
    k_scan2<<<1, 128>>>();                                                        // 4
    k_scan3<<<(N_NODES + 255) / 256, 256>>>();                                    // 5
    k_permute<<<(N_EDGES + 255) / 256, 256>>>(src, dst);                          // 6

    for (int l = 0; l < 3; l++) {
        if (l > 0) {
            k_mma<1><<<GRID_MMA, 512, SMEM_BYTES>>>(xsb + (size_t)(l - 1) * 128, XSD,
                                                    wimg + (size_t)(2 * l) * 4352,
                                                    gam[l - 1], bet[l - 1],
                                                    nullptr, nullptr, nullptr, nullptr, yb, 128, l, 1);
        }
        k_gather<<<(N_NODES + 7) / 8, 256>>>();
        k_mma<2><<<GRID_MMA, 512, SMEM_BYTES>>>(aggb, 128, wimg + (size_t)(2 * l + 1) * 4352,
                                                b1[l], nullptr, nullptr, nullptr, b2[l], batch,
                                                xsb + (size_t)l * 128, XSD, l, l < 2 ? 1 : 0);
    }

    k_mlp<<<GG, 128>>>(Wl1, bl1, Wl2, bl2,
                       gam[0], bet[0], gam[1], bet[1], gam[2], bet[2],
                       (float*)d_out);
}

// round 17
// speedup vs baseline: 1.1232x; 1.0251x over previous
#include <cuda_runtime.h>
#include <cuda_bf16.h>
#include <cstdint>

#define N_NODES 100000
#define N_EDGES 1600000
#define HID 128
#define GG 512
#define XSD 384
#define NB64 1563                       // ceil(100000/64)
#define GRID_MMA 296                    // persistent: 2 CTAs/SM x 148 SMs
#define KP 136                          // smem pitch in bf16 elems
#define A64 (64 * KP)                   // elems per 64-row A image
#define B128 (128 * KP)                 // elems per 128-row B image
#define SMEM_BYTES ((2 * A64 + 2 * B128) * 2 + 1024)   // 105472
#define NBLK1 98                        // ceil(100000/1024)

// ---------------- scratch (static device globals; no allocation) ----------------
__device__ float g_y[N_NODES * HID];      // pre-aggregation features (gather source)
__device__ float g_agg[N_NODES * HID];    // self + edge aggregation
__device__ float g_xs[N_NODES * XSD];     // per-layer raw (pre-BN-affine) outputs
__device__ uint4 g_wimg[6 * 4352];        // 6 weights x (hi+lo) bf16 images [n][k] pitch KP
__device__ float g_pooled[GG * XSD];
__device__ float g_sum[3 * HID];
__device__ float g_sumsq[3 * HID];
__device__ int   g_counts[GG];
// CSR scratch
__device__ int g_deg[NBLK1 * 1024];
__device__ int g_incl[NBLK1 * 1024];
__device__ int g_start[N_NODES];
__device__ int g_cur[N_NODES];
__device__ int g_ssrc[N_EDGES];
__device__ int g_bsum[128];

// ---------------- helpers ----------------
__device__ __forceinline__ void red_add_v2(float* p, float2 v) {
    asm volatile("red.global.add.v2.f32 [%0], {%1, %2};"
                 :: "l"(p), "f"(v.x), "f"(v.y) : "memory");
}
__device__ __forceinline__ void mma_bf16(float* c, uint32_t a0, uint32_t a1, uint32_t a2,
                                         uint32_t a3, uint32_t b0, uint32_t b1) {
    asm volatile(
        "mma.sync.aligned.m16n8k16.row.col.f32.bf16.bf16.f32 "
        "{%0,%1,%2,%3}, {%4,%5,%6,%7}, {%8,%9}, {%0,%1,%2,%3};"
        : "+f"(c[0]), "+f"(c[1]), "+f"(c[2]), "+f"(c[3])
        : "r"(a0), "r"(a1), "r"(a2), "r"(a3), "r"(b0), "r"(b1));
}
__device__ __forceinline__ void ldsm_x4(uint32_t* r, uint32_t addr) {
    asm volatile("ldmatrix.sync.aligned.m8n8.x4.shared.b16 {%0,%1,%2,%3}, [%4];"
                 : "=r"(r[0]), "=r"(r[1]), "=r"(r[2]), "=r"(r[3]) : "r"(addr));
}
__device__ __forceinline__ uint32_t pack_bf2(__nv_bfloat16 lo, __nv_bfloat16 hi) {
    return (uint32_t)__bfloat16_as_ushort(lo) | ((uint32_t)__bfloat16_as_ushort(hi) << 16);
}

// ---------------- weight prep + stat/pool/deg zero ----------------
__global__ void k_prep(const float* __restrict__ w0, const float* __restrict__ w1,
                       const float* __restrict__ w2, const float* __restrict__ w3,
                       const float* __restrict__ w4, const float* __restrict__ w5) {
    int bb = blockIdx.x;
    if (bb < 6) {
        const float* W = bb == 0 ? w0 : bb == 1 ? w1 : bb == 2 ? w2 : bb == 3 ? w3 : bb == 4 ? w4 : w5;
        __nv_bfloat16* img = ((__nv_bfloat16*)g_wimg) + (size_t)bb * 2 * B128;
        for (int idx = threadIdx.x; idx < 16384; idx += 256) {
            int k = idx >> 7, n = idx & 127;
            float w = W[idx];
            __nv_bfloat16 h = __float2bfloat16(w);
            __nv_bfloat16 l = __float2bfloat16(w - __bfloat162float(h));
            img[n * KP + k] = h;
            img[B128 + n * KP + k] = l;
        }
    } else if (bb == 6) {
        for (int i = threadIdx.x; i < 3 * HID; i += 256) { g_sum[i] = 0.f; g_sumsq[i] = 0.f; }
    } else if (bb < 199) {
        int idx = (bb - 7) * 256 + threadIdx.x;
        if (idx < GG * XSD / 4) ((float4*)g_pooled)[idx] = make_float4(0.f, 0.f, 0.f, 0.f);
    } else {
        int base = (bb - 199) * 1024 + threadIdx.x * 4;
        *(int4*)&g_deg[base] = make_int4(0, 0, 0, 0);
    }
}

// ---------------- CSR hist + graph counts ----------------
__global__ void k_hist(const int* __restrict__ dst, const int* __restrict__ batch) {
    if (blockIdx.x < 6250) {
        int e = blockIdx.x * 256 + threadIdx.x;
        if (e < N_EDGES) atomicAdd(&g_deg[dst[e]], 1);
    } else {
        __shared__ int h[GG];
        int t = threadIdx.x;
        for (int i = t; i < GG; i += 256) h[i] = 0;
        __syncthreads();
        for (int i = t; i < N_NODES; i += 256) atomicAdd(&h[batch[i]], 1);
        __syncthreads();
        for (int i = t; i < GG; i += 256) g_counts[i] = h[i];
    }
}

__global__ void __launch_bounds__(256) k_scan1() {
    __shared__ int s[256];
    int b = blockIdx.x, t = threadIdx.x;
    int base = b * 1024 + t * 4;
    int v0 = g_deg[base], v1 = g_deg[base + 1], v2 = g_deg[base + 2], v3 = g_deg[base + 3];
    int s0 = v0, s1 = s0 + v1, s2 = s1 + v2, s3 = s2 + v3;
    s[t] = s3;
    __syncthreads();
    for (int off = 1; off < 256; off <<= 1) {
        int x = (t >= off) ? s[t - off] : 0;
        __syncthreads();
        if (t >= off) s[t] += x;
        __syncthreads();
    }
    int prev = (t > 0) ? s[t - 1] : 0;
    g_incl[base] = prev + s0; g_incl[base + 1] = prev + s1;
    g_incl[base + 2] = prev + s2; g_incl[base + 3] = prev + s3;
    if (t == 255) g_bsum[b] = s[255];
}
__global__ void __launch_bounds__(128) k_scan2() {
    __shared__ int s[128];
    int t = threadIdx.x;
    s[t] = (t < NBLK1) ? g_bsum[t] : 0;
    __syncthreads();
    for (int off = 1; off < 128; off <<= 1) {
        int x = (t >= off) ? s[t - off] : 0;
        __syncthreads();
        if (t >= off) s[t] += x;
        __syncthreads();
    }
    if (t < NBLK1) g_bsum[t] = (t > 0) ? s[t - 1] : 0;   // exclusive block offsets
}
__global__ void k_scan3() {
    int i = blockIdx.x * blockDim.x + threadIdx.x;
    if (i >= N_NODES) return;
    int st = g_incl[i] - g_deg[i] + g_bsum[i >> 10];
    g_start[i] = st;
    g_cur[i] = st;
}
__global__ void k_permute(const int* __restrict__ src, const int* __restrict__ dst) {
    int e = blockIdx.x * blockDim.x + threadIdx.x;
    if (e >= N_EDGES) return;
    int p = atomicAdd(&g_cur[dst[e]], 1);
    g_ssrc[p] = src[e];
}

// ---------------- gather: agg[d] = y[d] + sum_{e: dst=d} y[src[e]]  (fp32, unroll 4) ----------------
__global__ void __launch_bounds__(256) k_gather() {
    int d = blockIdx.x * 8 + (threadIdx.x >> 5);
    if (d >= N_NODES) return;
    int lane = threadIdx.x & 31;
    const float4* Y = (const float4*)g_y;
    float4 acc = Y[(size_t)d * 32 + lane];          // self term
    int s = g_start[d], n = g_deg[d];
    int e = s, end = s + n;
    for (; e + 4 <= end; e += 4) {
        int i0 = g_ssrc[e], i1 = g_ssrc[e + 1], i2 = g_ssrc[e + 2], i3 = g_ssrc[e + 3];
        float4 v0 = Y[(size_t)i0 * 32 + lane];
        float4 v1 = Y[(size_t)i1 * 32 + lane];
        float4 v2 = Y[(size_t)i2 * 32 + lane];
        float4 v3 = Y[(size_t)i3 * 32 + lane];
        acc.x += v0.x + v1.x + v2.x + v3.x;
        acc.y += v0.y + v1.y + v2.y + v3.y;
        acc.z += v0.z + v1.z + v2.z + v3.z;
        acc.w += v0.w + v1.w + v2.w + v3.w;
    }
    for (; e < end; e++) {
        int i0 = g_ssrc[e];
        float4 v0 = Y[(size_t)i0 * 32 + lane];
        acc.x += v0.x; acc.y += v0.y; acc.z += v0.z; acc.w += v0.w;
    }
    ((float4*)g_agg)[(size_t)d * 32 + lane] = acc;
}

// ---------------- persistent fused bf16x3 GEMM, M-tile 64, 512 threads, warp tile 16x32 ----------------
// MODE 0: A = x,                         epi: v = D + W1[z] + W1[100+z]; write y
// MODE 1: A = xs_prev*scale+shift (affine from raw stats), epi: v = D;  write y
// MODE 2: A = relu(agg + b1),            epi: v = relu(D + b2);
//         write xs (if write_xs) + BN stats + pooled red-add
template <int MODE>
__global__ void __launch_bounds__(512, 2) k_mma(
    const float* __restrict__ A, int lda,
    const uint4* __restrict__ Wimg,
    const float* __restrict__ aux0,   // MODE1: gamma  MODE2: b1
    const float* __restrict__ aux1,   // MODE1: beta
    const int* __restrict__ z,        // MODE0
    const float* __restrict__ Wfull,  // MODE0: full W1_0
    const float* __restrict__ b2,     // MODE2
    const int* __restrict__ batch,    // MODE2
    float* __restrict__ out0, int ld0,
    int layer, int write_xs)
{
    extern __shared__ char smem[];
    __nv_bfloat16* sAh = (__nv_bfloat16*)smem;
    __nv_bfloat16* sAl = sAh + A64;
    __nv_bfloat16* sBh = sAl + A64;
    float* s_sum = (float*)(smem + (2 * A64 + 2 * B128) * 2);   // MODE2: stats  MODE1: scale
    float* s_sq  = s_sum + 128;                                 // MODE2: stats  MODE1: shift
    const int tid = threadIdx.x;
    const int wid = tid >> 5, lane = tid & 31;

    if (MODE == 2 && tid < 256) { s_sum[tid & 127] = 0.f; s_sq[tid & 127] = 0.f; }
    if (MODE == 1 && tid < 128) {
        const float invN = 1.0f / (float)N_NODES;
        int so = (layer - 1) * 128 + tid;
        float mu = g_sum[so] * invN;
        float var = g_sumsq[so] * invN - mu * mu;
        float s = aux0[tid] * rsqrtf(fmaxf(var, 0.f) + 1e-5f);
        s_sum[tid] = s;
        s_sq[tid] = aux1[tid] - mu * s;
    }

    // ---- copy pre-split B images ONCE (hi+lo = 4352 uint4) ----
    uint4* sB4 = (uint4*)sBh;
#pragma unroll
    for (int j = 0; j < 9; j++) {
        int idx = tid + j * 512;
        if (idx < 4352) sB4[idx] = Wimg[idx];
    }
    __syncthreads();   // B ready; MODE1 affine ready; MODE2 stats zeroed

    // fixed per-thread addressing
    const int wm = wid & 3, wn = wid >> 2;
    const int lr = lane >> 2, lq = lane & 3;
    const int lrow = lane & 7, lsel = lane >> 3;   // ldmatrix lane mapping
    const uint32_t sAh_u = (uint32_t)__cvta_generic_to_shared(sAh);
    const uint32_t sBh_u = (uint32_t)__cvta_generic_to_shared(sBh);
    const uint32_t loA = (uint32_t)(A64 * 2);     // bytes hi->lo (A)
    const uint32_t loB = (uint32_t)(B128 * 2);    // bytes hi->lo (B)
    uint32_t aBase;
    {
        int ar = wm * 16 + ((lsel & 1) << 3) + lrow;
        int ac = (lsel >> 1) << 3;
        aBase = sAh_u + (uint32_t)(ar * KP + ac) * 2;
    }
    uint32_t bBase[2];
#pragma unroll
    for (int p = 0; p < 2; p++) {
        int br = wn * 32 + p * 16 + ((lsel >> 1) << 3) + lrow;
        int bc = (lsel & 1) << 3;
        bBase[p] = sBh_u + (uint32_t)(br * KP + bc) * 2;
    }

    // ---- persistent loop over M-tiles ----
    for (int mb = blockIdx.x; mb < NB64; mb += GRID_MMA) {
        const int row0 = mb * 64;

        // ---- load A tile (64 rows) with fused transforms, split bf16 hi/lo ----
#pragma unroll
        for (int j = 0; j < 4; j++) {
            int v4 = tid + j * 512;
            int r = v4 >> 5, c4 = v4 & 31;
            int row = row0 + r;
            float4 a = make_float4(0.f, 0.f, 0.f, 0.f);
            if (row < N_NODES) {
                a = *(const float4*)(A + (size_t)row * lda + c4 * 4);
                if (MODE == 1) {
                    float4 sc = ((const float4*)s_sum)[c4];
                    float4 sh = ((const float4*)s_sq)[c4];
                    a.x = fmaf(a.x, sc.x, sh.x); a.y = fmaf(a.y, sc.y, sh.y);
                    a.z = fmaf(a.z, sc.z, sh.z); a.w = fmaf(a.w, sc.w, sh.w);
                } else if (MODE == 2) {
                    float4 bb = ((const float4*)aux0)[c4];
                    a.x = fmaxf(a.x + bb.x, 0.f); a.y = fmaxf(a.y + bb.y, 0.f);
                    a.z = fmaxf(a.z + bb.z, 0.f); a.w = fmaxf(a.w + bb.w, 0.f);
                }
            }
            __nv_bfloat16 h0 = __float2bfloat16(a.x), h1 = __float2bfloat16(a.y);
            __nv_bfloat16 h2 = __float2bfloat16(a.z), h3 = __float2bfloat16(a.w);
            __nv_bfloat16 l0 = __float2bfloat16(a.x - __bfloat162float(h0));
            __nv_bfloat16 l1 = __float2bfloat16(a.y - __bfloat162float(h1));
            __nv_bfloat16 l2 = __float2bfloat16(a.z - __bfloat162float(h2));
            __nv_bfloat16 l3 = __float2bfloat16(a.w - __bfloat162float(h3));
            *(uint2*)&sAh[r * KP + c4 * 4] = make_uint2(pack_bf2(h0, h1), pack_bf2(h2, h3));
            *(uint2*)&sAl[r * KP + c4 * 4] = make_uint2(pack_bf2(l0, l1), pack_bf2(l2, l3));
        }
        __syncthreads();

        // ---- mainloop ----
        float acc[4][4];
#pragma unroll
        for (int nb = 0; nb < 4; nb++)
#pragma unroll
            for (int i = 0; i < 4; i++) acc[nb][i] = 0.f;

#pragma unroll
        for (int ks = 0; ks < 8; ks++) {
            const uint32_t off = (uint32_t)ks * 32;    // 16 bf16 = 32 bytes per K step
            uint32_t ah[4], al[4], bh[2][4], bl[2][4];
            ldsm_x4(ah, aBase + off);
            ldsm_x4(al, aBase + off + loA);
#pragma unroll
            for (int p = 0; p < 2; p++) {
                ldsm_x4(bh[p], bBase[p] + off);
                ldsm_x4(bl[p], bBase[p] + off + loB);
            }
#pragma unroll
            for (int p = 0; p < 2; p++) {
                mma_bf16(acc[2 * p],     ah[0], ah[1], ah[2], ah[3], bh[p][0], bh[p][1]);
                mma_bf16(acc[2 * p],     al[0], al[1], al[2], al[3], bh[p][0], bh[p][1]);
                mma_bf16(acc[2 * p],     ah[0], ah[1], ah[2], ah[3], bl[p][0], bl[p][1]);
                mma_bf16(acc[2 * p + 1], ah[0], ah[1], ah[2], ah[3], bh[p][2], bh[p][3]);
                mma_bf16(acc[2 * p + 1], al[0], al[1], al[2], al[3], bh[p][2], bh[p][3]);
                mma_bf16(acc[2 * p + 1], ah[0], ah[1], ah[2], ah[3], bl[p][2], bl[p][3]);
            }
        }
        __syncthreads();   // all ldsm done before next tile overwrites A

        // ---- epilogue for this tile ----
        const int r0 = row0 + wm * 16 + lr;
        const int r1 = r0 + 8;
        int zi0 = 0, zi1 = 0, bt0 = 0, bt1 = 0;
        if (MODE == 0) {
            if (r0 < N_NODES) zi0 = z[r0];
            if (r1 < N_NODES) zi1 = z[r1];
        }
        if (MODE == 2) {
            if (r0 < N_NODES) bt0 = batch[r0];
            if (r1 < N_NODES) bt1 = batch[r1];
        }
#pragma unroll
        for (int nb = 0; nb < 4; nb++) {
            const int c = wn * 32 + nb * 8 + 2 * lq;
            float2 v0 = make_float2(acc[nb][0], acc[nb][1]);
            float2 v1 = make_float2(acc[nb][2], acc[nb][3]);
            if (MODE == 0) {
                if (r0 < N_NODES) {
                    float2 e = *(const float2*)&Wfull[(size_t)zi0 * 128 + c];
                    float2 f = *(const float2*)&Wfull[(size_t)(100 + zi0) * 128 + c];
                    v0.x += e.x + f.x; v0.y += e.y + f.y;
                }
                if (r1 < N_NODES) {
                    float2 e = *(const float2*)&Wfull[(size_t)zi1 * 128 + c];
                    float2 f = *(const float2*)&Wfull[(size_t)(100 + zi1) * 128 + c];
                    v1.x += e.x + f.x; v1.y += e.y + f.y;
                }
            }
            if (MODE == 2) {
                float2 bb = *(const float2*)&b2[c];
                v0.x = fmaxf(v0.x + bb.x, 0.f); v0.y = fmaxf(v0.y + bb.y, 0.f);
                v1.x = fmaxf(v1.x + bb.x, 0.f); v1.y = fmaxf(v1.y + bb.y, 0.f);
            }
            float ps0 = 0.f, ps1 = 0.f, pq0 = 0.f, pq1 = 0.f;
            if (r0 < N_NODES) {
                if (MODE != 2) {
                    *(float2*)&out0[(size_t)r0 * ld0 + c] = v0;
                } else {
                    if (write_xs) *(float2*)&out0[(size_t)r0 * ld0 + c] = v0;
                    red_add_v2(&g_pooled[(size_t)bt0 * XSD + layer * 128 + c], v0);
                    ps0 += v0.x; ps1 += v0.y; pq0 += v0.x * v0.x; pq1 += v0.y * v0.y;
                }
            }
            if (r1 < N_NODES) {
                if (MODE != 2) {
                    *(float2*)&out0[(size_t)r1 * ld0 + c] = v1;
                } else {
                    if (write_xs) *(float2*)&out0[(size_t)r1 * ld0 + c] = v1;
                    red_add_v2(&g_pooled[(size_t)bt1 * XSD + layer * 128 + c], v1);
                    ps0 += v1.x; ps1 += v1.y; pq0 += v1.x * v1.x; pq1 += v1.y * v1.y;
                }
            }
            if (MODE == 2) {
                atomicAdd(&s_sum[c], ps0);
                atomicAdd(&s_sum[c + 1], ps1);
                atomicAdd(&s_sq[c], pq0);
                atomicAdd(&s_sq[c + 1], pq1);
            }
        }
    }

    if (MODE == 2) {
        __syncthreads();
        if (tid < 128) {
            atomicAdd(&g_sum[layer * 128 + tid], s_sum[tid]);
            atomicAdd(&g_sumsq[layer * 128 + tid], s_sq[tid]);
        }
    }
}

// ---------------- final MLP (BN affine computed inline, folded into pooled sums) ----------------
__global__ void __launch_bounds__(128) k_mlp(
    const float* __restrict__ Wl1, const float* __restrict__ bl1,
    const float* __restrict__ Wl2, const float* __restrict__ bl2,
    const float* __restrict__ gam0, const float* __restrict__ bet0,
    const float* __restrict__ gam1, const float* __restrict__ bet1,
    const float* __restrict__ gam2, const float* __restrict__ bet2,
    float* __restrict__ out)
{
    int g = blockIdx.x;
    int c = threadIdx.x;
    __shared__ float sp[XSD];
    __shared__ float red[128];
    const float invN = 1.0f / (float)N_NODES;
    float cnt = (float)g_counts[g];
    float inv = 1.0f / fmaxf(cnt, 1.0f);
    for (int k = c; k < XSD; k += 128) {
        int l = k >> 7, ch = k & 127;
        const float* gm = l == 0 ? gam0 : l == 1 ? gam1 : gam2;
        const float* bt = l == 0 ? bet0 : l == 1 ? bet1 : bet2;
        float mu = g_sum[k] * invN;
        float var = g_sumsq[k] * invN - mu * mu;
        float s = gm[ch] * rsqrtf(fmaxf(var, 0.f) + 1e-5f);
        float sh = bt[ch] - mu * s;
        sp[k] = (g_pooled[(size_t)g * XSD + k] * s + cnt * sh) * inv;
    }
    __syncthreads();
    float acc = bl1[c];
    for (int k = 0; k < XSD; k++) acc += sp[k] * Wl1[(size_t)k * 128 + c];
    red[c] = fmaxf(acc, 0.f) * Wl2[c];
    __syncthreads();
    for (int s = 64; s > 0; s >>= 1) {
        if (c < s) red[c] += red[c + s];
        __syncthreads();
    }
    if (c == 0) out[g] = red[0] + bl2[0];
}

// ---------------- host ----------------
extern "C" void kernel_launch(void* const* d_in, const int* in_sizes, int n_in,
                              void* d_out, int out_size) {
    (void)in_sizes; (void)n_in; (void)out_size;
    const float* x     = (const float*)d_in[0];
    const int*   z     = (const int*)d_in[1];
    const int*   ei    = (const int*)d_in[2];
    const int*   batch = (const int*)d_in[3];
    const float *W1[3], *b1[3], *W2[3], *b2[3], *gam[3], *bet[3];
    for (int l = 0; l < 3; l++) {
        W1[l]  = (const float*)d_in[4 + 6 * l];
        b1[l]  = (const float*)d_in[5 + 6 * l];
        W2[l]  = (const float*)d_in[6 + 6 * l];
        b2[l]  = (const float*)d_in[7 + 6 * l];
        gam[l] = (const float*)d_in[8 + 6 * l];
        bet[l] = (const float*)d_in[9 + 6 * l];
    }
    const float* Wl1 = (const float*)d_in[22];
    const float* bl1 = (const float*)d_in[23];
    const float* Wl2 = (const float*)d_in[24];
    const float* bl2 = (const float*)d_in[25];
    const int* src = ei;
    const int* dst = ei + N_EDGES;

    void *yp, *aggp, *xsp, *wp;
    cudaGetSymbolAddress(&yp, g_y);
    cudaGetSymbolAddress(&aggp, g_agg);
    cudaGetSymbolAddress(&xsp, g_xs);
    cudaGetSymbolAddress(&wp, g_wimg);
    float* yb   = (float*)yp;
    float* aggb = (float*)aggp;
    float* xsb  = (float*)xsp;
    uint4* wimg = (uint4*)wp;

    cudaFuncSetAttribute(k_mma<0>, cudaFuncAttributeMaxDynamicSharedMemorySize, SMEM_BYTES);
    cudaFuncSetAttribute(k_mma<1>, cudaFuncAttributeMaxDynamicSharedMemorySize, SMEM_BYTES);
    cudaFuncSetAttribute(k_mma<2>, cudaFuncAttributeMaxDynamicSharedMemorySize, SMEM_BYTES);

    // fork-join: CSR build runs on a side stream, concurrent with k_mma<0>.
    cudaStream_t s2;
    cudaEvent_t evA, evB;
    cudaStreamCreateWithFlags(&s2, cudaStreamNonBlocking);
    cudaEventCreateWithFlags(&evA, cudaEventDisableTiming);
    cudaEventCreateWithFlags(&evB, cudaEventDisableTiming);

    k_prep<<<297, 256>>>(W1[0] + 200 * 128, W2[0], W1[1], W2[1], W1[2], W2[2]);
    cudaEventRecord(evA, 0);
    cudaStreamWaitEvent(s2, evA, 0);

    // CSR chain on side stream
    k_hist<<<6251, 256, 0, s2>>>(dst, batch);
    k_scan1<<<NBLK1, 256, 0, s2>>>();
    k_scan2<<<1, 128, 0, s2>>>();
    k_scan3<<<(N_NODES + 255) / 256, 256, 0, s2>>>();
    k_permute<<<(N_EDGES + 255) / 256, 256, 0, s2>>>(src, dst);
    cudaEventRecord(evB, s2);

    // layer-0 GEMM on main stream, concurrent with CSR build
    k_mma<0><<<GRID_MMA, 512, SMEM_BYTES>>>(x, 128, wimg, nullptr, nullptr,
                                            z, W1[0], nullptr, nullptr, yb, 128, 0, 1);
    cudaStreamWaitEvent(0, evB, 0);   // join before first gather

    for (int l = 0; l < 3; l++) {
        if (l > 0) {
            k_mma<1><<<GRID_MMA, 512, SMEM_BYTES>>>(xsb + (size_t)(l - 1) * 128, XSD,
                                                    wimg + (size_t)(2 * l) * 4352,
                                                    gam[l - 1], bet[l - 1],
                                                    nullptr, nullptr, nullptr, nullptr, yb, 128, l, 1);
        }
        k_gather<<<(N_NODES + 7) / 8, 256>>>();
        k_mma<2><<<GRID_MMA, 512, SMEM_BYTES>>>(aggb, 128, wimg + (size_t)(2 * l + 1) * 4352,
                                                b1[l], nullptr, nullptr, nullptr, b2[l], batch,
                                                xsb + (size_t)l * 128, XSD, l, l < 2 ? 1 : 0);
    }

    k_mlp<<<GG, 128>>>(Wl1, bl1, Wl2, bl2,
                       gam[0], bet[0], gam[1], bet[1], gam[2], bet[2],
                       (float*)d_out);

    cudaEventDestroy(evA);
    cudaEventDestroy(evB);
    cudaStreamDestroy(s2);
}